// round 3
// baseline (speedup 1.0000x reference)
#include <cuda_runtime.h>
#include <cuda_bf16.h>
#include <cstdint>

#define Bn 8
#define Sn 1024
#define Dn 1024
#define Hn 16
#define HDn 64
#define Mtot (Bn * Sn)   // 8192

// ---------------------------------------------------------------------------
// Scratch (__device__ globals; allocation-free rule)
// ---------------------------------------------------------------------------
__device__ float g_q[Bn * Hn * Sn * HDn];
__device__ float g_k[Bn * Hn * Sn * HDn];
__device__ float g_v[Bn * Hn * Sn * HDn];

__device__ __align__(16) __nv_bfloat16 g_hs_hi[Mtot * Dn];
__device__ __align__(16) __nv_bfloat16 g_hs_lo[Mtot * Dn];
// W^T split buffers, reused across the 3 sequential GEMMs
__device__ __align__(16) __nv_bfloat16 g_wt_hi[Dn * Dn];
__device__ __align__(16) __nv_bfloat16 g_wt_lo[Dn * Dn];

// ---------------------------------------------------------------------------
// Helpers (sm_80+ PTX only — no tcgen05, works at compute_103 base target)
// ---------------------------------------------------------------------------
__device__ __forceinline__ uint32_t smem_u32(const void* p) {
    uint32_t a;
    asm("{ .reg .u64 t; cvta.to.shared.u64 t, %1; cvt.u32.u64 %0, t; }"
        : "=r"(a) : "l"(p));
    return a;
}

#define CP_ASYNC16(dst, src) \
    asm volatile("cp.async.cg.shared.global [%0], [%1], 16;" \
                 :: "r"(dst), "l"(src) : "memory")
#define CP_COMMIT() asm volatile("cp.async.commit_group;" ::: "memory")
#define CP_WAIT(n)  asm volatile("cp.async.wait_group %0;" :: "n"(n) : "memory")

__device__ __forceinline__ void ldsm_x4(uint32_t (&r)[4], uint32_t addr) {
    asm volatile("ldmatrix.sync.aligned.m8n8.x4.shared.b16 {%0,%1,%2,%3}, [%4];"
                 : "=r"(r[0]), "=r"(r[1]), "=r"(r[2]), "=r"(r[3]) : "r"(addr));
}

__device__ __forceinline__ void mma_bf16(float (&c)[4], const uint32_t (&a)[4],
                                         uint32_t b0, uint32_t b1) {
    asm volatile(
        "mma.sync.aligned.m16n8k16.row.col.f32.bf16.bf16.f32 "
        "{%0,%1,%2,%3}, {%4,%5,%6,%7}, {%8,%9}, {%0,%1,%2,%3};"
        : "+f"(c[0]), "+f"(c[1]), "+f"(c[2]), "+f"(c[3])
        : "r"(a[0]), "r"(a[1]), "r"(a[2]), "r"(a[3]), "r"(b0), "r"(b1));
}

// ---------------------------------------------------------------------------
// fp32 -> bf16 hi/lo split (elementwise), 4 elems/thread
// ---------------------------------------------------------------------------
__global__ void split_kernel(const float* __restrict__ x,
                             __nv_bfloat16* __restrict__ hi,
                             __nv_bfloat16* __restrict__ lo, int n4) {
    int i = blockIdx.x * blockDim.x + threadIdx.x;
    if (i >= n4) return;
    float4 v = ((const float4*)x)[i];
    float f[4] = {v.x, v.y, v.z, v.w};
#pragma unroll
    for (int j = 0; j < 4; j++) {
        __nv_bfloat16 h = __float2bfloat16(f[j]);
        hi[i * 4 + j] = h;
        lo[i * 4 + j] = __float2bfloat16(f[j] - __bfloat162float(h));
    }
}

// fp32 W[k][n] -> bf16 hi/lo of W^T [n][k], via smem transpose
__global__ void splitT_kernel(const float* __restrict__ W,
                              __nv_bfloat16* __restrict__ hi,
                              __nv_bfloat16* __restrict__ lo) {
    __shared__ float t[32][33];
    int n = blockIdx.x * 32 + threadIdx.x;
    int k = blockIdx.y * 32 + threadIdx.y;
    t[threadIdx.y][threadIdx.x] = W[k * Dn + n];
    __syncthreads();
    int nn = blockIdx.x * 32 + threadIdx.y;
    int kk = blockIdx.y * 32 + threadIdx.x;
    float v = t[threadIdx.x][threadIdx.y];
    __nv_bfloat16 h = __float2bfloat16(v);
    hi[nn * Dn + kk] = h;
    lo[nn * Dn + kk] = __float2bfloat16(v - __bfloat162float(h));
}

// ---------------------------------------------------------------------------
// mma.sync GEMM: D[8192x1024] = A @ W + bias, split-bf16 (3 MMAs / position).
// BM=128, BN=128, BK=16, 256 threads (8 warps, 4m x 2n), warp tile 32x64.
// Double-buffered cp.async. Scatter to [B,H,S,HD].
// ---------------------------------------------------------------------------
#define KPAD 24    // padded row stride (bf16 elems) for a 16-wide k tile

__global__ __launch_bounds__(256) void qkv_gemm_mma(
    const __nv_bfloat16* __restrict__ Ahi, const __nv_bfloat16* __restrict__ Alo,
    const __nv_bfloat16* __restrict__ Whi, const __nv_bfloat16* __restrict__ Wlo,
    const float* __restrict__ bias, int sel)
{
    // [stage][matrix: Ahi,Alo,Bhi,Blo][128 rows * KPAD]  = 49152 bytes
    __shared__ __nv_bfloat16 sm[2][4][128 * KPAD];

    float* out = (sel == 0) ? g_q : (sel == 1) ? g_k : g_v;

    const int tid = threadIdx.x;
    const int wid = tid >> 5;
    const int lid = tid & 31;

    const int blockRow = blockIdx.y * 128;
    const int blockCol = blockIdx.x * 128;

    const int warpM = (wid & 3) * 32;
    const int warpN = (wid >> 2) * 64;

    // Per-thread load mapping: one 16B chunk per matrix per stage
    const int ldRow = tid >> 1;        // 0..127
    const int ldHalf = tid & 1;        // which 8-elem half of the 16-elem row
    const __nv_bfloat16* gsrc[4] = {
        Ahi + (size_t)(blockRow + ldRow) * Dn + ldHalf * 8,
        Alo + (size_t)(blockRow + ldRow) * Dn + ldHalf * 8,
        Whi + (size_t)(blockCol + ldRow) * Dn + ldHalf * 8,
        Wlo + (size_t)(blockCol + ldRow) * Dn + ldHalf * 8};

    uint32_t sdst[4];
#pragma unroll
    for (int m = 0; m < 4; m++)
        sdst[m] = smem_u32(&sm[0][m][ldRow * KPAD + ldHalf * 8]);
    const uint32_t stageStride = 4 * 128 * KPAD * 2;   // bytes between stages

    // ldmatrix address offsets (within a [128*KPAD] matrix), in bytes
    // A: row = warpM + mi*16 + (lid&15), colByte = (lid>>4)*16
    const uint32_t aOff0 = ((warpM + (lid & 15)) * KPAD + (lid >> 4) * 8) * 2;
    // B: row = warpN + g*16 + (lid&7) + ((lid>>4)*8), colByte = ((lid>>3)&1)*16
    const uint32_t bOffBase =
        ((warpN + (lid & 7) + ((lid >> 4) * 8)) * KPAD + ((lid >> 3) & 1) * 8) * 2;

    const uint32_t smBase = smem_u32(&sm[0][0][0]);
    const uint32_t matStride = 128 * KPAD * 2;   // bytes between matrices

    float acc[2][8][4];
#pragma unroll
    for (int mi = 0; mi < 2; mi++)
#pragma unroll
        for (int ni = 0; ni < 8; ni++)
#pragma unroll
            for (int j = 0; j < 4; j++) acc[mi][ni][j] = 0.f;

    // Prologue: stage 0
#pragma unroll
    for (int m = 0; m < 4; m++) CP_ASYNC16(sdst[m], gsrc[m]);
    CP_COMMIT();

    const int KT = Dn / 16;   // 64
    for (int kt = 0; kt < KT; kt++) {
        const int st = kt & 1;
        if (kt < KT - 1) {
            const int koff = (kt + 1) * 16;
            const uint32_t soff = ((kt + 1) & 1) * stageStride;
#pragma unroll
            for (int m = 0; m < 4; m++) CP_ASYNC16(sdst[m] + soff, gsrc[m] + koff);
            CP_COMMIT();
            CP_WAIT(1);
        } else {
            CP_WAIT(0);
        }
        __syncthreads();

        const uint32_t stBase = smBase + st * stageStride;

        // A fragments: [mi][hi/lo]
        uint32_t ahi[2][4], alo[2][4];
#pragma unroll
        for (int mi = 0; mi < 2; mi++) {
            ldsm_x4(ahi[mi], stBase + 0 * matStride + aOff0 + mi * 16 * KPAD * 2);
            ldsm_x4(alo[mi], stBase + 1 * matStride + aOff0 + mi * 16 * KPAD * 2);
        }

#pragma unroll
        for (int g = 0; g < 4; g++) {   // 16-n groups
            uint32_t bhi[4], blo[4];
            const uint32_t bo = bOffBase + g * 16 * KPAD * 2;
            ldsm_x4(bhi, stBase + 2 * matStride + bo);
            ldsm_x4(blo, stBase + 3 * matStride + bo);
#pragma unroll
            for (int nt = 0; nt < 2; nt++) {
                const int ni = g * 2 + nt;
#pragma unroll
                for (int mi = 0; mi < 2; mi++) {
                    mma_bf16(acc[mi][ni], ahi[mi], bhi[nt * 2], bhi[nt * 2 + 1]);
                    mma_bf16(acc[mi][ni], ahi[mi], blo[nt * 2], blo[nt * 2 + 1]);
                    mma_bf16(acc[mi][ni], alo[mi], bhi[nt * 2], bhi[nt * 2 + 1]);
                }
            }
        }
        __syncthreads();
    }

    // Epilogue: scatter to [B,H,S,HD] with bias. Acc layout per mma tile:
    // c0,c1 -> (row = lid/4,     col = (lid%4)*2 .. +1)
    // c2,c3 -> (row = lid/4 + 8, col = same)
#pragma unroll
    for (int mi = 0; mi < 2; mi++) {
#pragma unroll
        for (int ni = 0; ni < 8; ni++) {
            const int n = blockCol + warpN + ni * 8 + (lid & 3) * 2;
            const int h = n >> 6;
            const int hd = n & 63;
            const float2 bv = *(const float2*)(bias + n);
#pragma unroll
            for (int half = 0; half < 2; half++) {
                const int m = blockRow + warpM + mi * 16 + (lid >> 2) + half * 8;
                const int b = m >> 10;
                const int s = m & 1023;
                float2 v;
                v.x = acc[mi][ni][half * 2 + 0] + bv.x;
                v.y = acc[mi][ni][half * 2 + 1] + bv.y;
                *(float2*)(out + ((size_t)(b * Hn + h) * Sn + s) * HDn + hd) = v;
            }
        }
    }
}

// ---------------------------------------------------------------------------
// Flash-style attention (fp32): grid (S/64, B*H), 128 threads.
// ---------------------------------------------------------------------------
__global__ __launch_bounds__(128) void attn_kernel(
    const float* __restrict__ mask, float* __restrict__ out)
{
    __shared__ float Qs[64][68];
    __shared__ float Ks[32][64];
    __shared__ float Vs[32][64];
    __shared__ float Ps[64][33];
    __shared__ float mrow[64], lrow[64], arow[64];

    const int tid = threadIdx.x;
    const int qt = blockIdx.x;
    const int bh = blockIdx.y;
    const int b = bh >> 4;

    const float* Qg = g_q + (size_t)bh * Sn * HDn + (size_t)qt * 64 * HDn;
    const float* Kg = g_k + (size_t)bh * Sn * HDn;
    const float* Vg = g_v + (size_t)bh * Sn * HDn;

    const int r = tid & 63;
    const int half = tid >> 6;
    const int csBase = half * 16;
    const int cdBase = half * 32;

#pragma unroll
    for (int i = 0; i < 8; i++) {
        int lin = tid + i * 128;
        int row = lin >> 4;
        int c4 = (lin & 15) << 2;
        *(float4*)&Qs[row][c4] = *(const float4*)(Qg + row * HDn + c4);
    }
    if (tid < 64) { mrow[tid] = -1e30f; lrow[tid] = 0.f; }

    float acc[32];
#pragma unroll
    for (int d = 0; d < 32; d++) acc[d] = 0.f;
    __syncthreads();

    for (int kt = 0; kt < Sn / 32; kt++) {
#pragma unroll
        for (int i = 0; i < 4; i++) {
            int lin = tid + i * 128;
            int row = lin >> 4;
            int c4 = (lin & 15) << 2;
            *(float4*)&Ks[row][c4] = *(const float4*)(Kg + (size_t)kt * 32 * HDn + row * HDn + c4);
            *(float4*)&Vs[row][c4] = *(const float4*)(Vg + (size_t)kt * 32 * HDn + row * HDn + c4);
        }
        __syncthreads();

        float sreg[16];
#pragma unroll
        for (int j = 0; j < 16; j++) sreg[j] = 0.f;
#pragma unroll
        for (int k4 = 0; k4 < 16; k4++) {
            float4 q = *(const float4*)&Qs[r][k4 << 2];
#pragma unroll
            for (int j = 0; j < 16; j++) {
                float4 kv = *(const float4*)&Ks[csBase + j][k4 << 2];
                sreg[j] += q.x * kv.x + q.y * kv.y + q.z * kv.z + q.w * kv.w;
            }
        }
        const float scale = 0.125f;
#pragma unroll
        for (int j = 0; j < 16; j++) {
            int col = csBase + j;
            Ps[r][col] = sreg[j] * scale + mask[b * Sn + kt * 32 + col];
        }
        __syncthreads();

        if (tid < 64) {
            float mold = mrow[tid];
            float mt = mold;
#pragma unroll 8
            for (int j = 0; j < 32; j++) mt = fmaxf(mt, Ps[tid][j]);
            float a = __expf(mold - mt);
            float sum = 0.f;
#pragma unroll 8
            for (int j = 0; j < 32; j++) {
                float p = __expf(Ps[tid][j] - mt);
                Ps[tid][j] = p;
                sum += p;
            }
            lrow[tid] = lrow[tid] * a + sum;
            mrow[tid] = mt;
            arow[tid] = a;
        }
        __syncthreads();

        float a = arow[r];
#pragma unroll
        for (int d = 0; d < 32; d++) acc[d] *= a;
#pragma unroll 4
        for (int j = 0; j < 32; j++) {
            float p = Ps[r][j];
#pragma unroll
            for (int d4 = 0; d4 < 8; d4++) {
                float4 v = *(const float4*)&Vs[j][cdBase + (d4 << 2)];
                acc[(d4 << 2) + 0] += p * v.x;
                acc[(d4 << 2) + 1] += p * v.y;
                acc[(d4 << 2) + 2] += p * v.z;
                acc[(d4 << 2) + 3] += p * v.w;
            }
        }
        __syncthreads();
    }

    const float inv = 1.f / lrow[r];
    const int qglob = qt * 64 + r;
    const int h = bh & 15;
    float* op = out + ((size_t)b * Sn + qglob) * Dn + h * HDn + cdBase;
#pragma unroll
    for (int d4 = 0; d4 < 8; d4++) {
        float4 v;
        v.x = acc[(d4 << 2) + 0] * inv;
        v.y = acc[(d4 << 2) + 1] * inv;
        v.z = acc[(d4 << 2) + 2] * inv;
        v.w = acc[(d4 << 2) + 3] * inv;
        *(float4*)(op + (d4 << 2)) = v;
    }
}

// ---------------------------------------------------------------------------
// Launch
// ---------------------------------------------------------------------------
extern "C" void kernel_launch(void* const* d_in, const int* in_sizes, int n_in,
                              void* d_out, int out_size)
{
    const float* hs   = (const float*)d_in[0];
    const float* mask = (const float*)d_in[1];
    const float* Wq   = (const float*)d_in[2];
    const float* bq   = (const float*)d_in[3];
    const float* Wk   = (const float*)d_in[4];
    const float* bk   = (const float*)d_in[5];
    const float* Wv   = (const float*)d_in[6];
    const float* bv   = (const float*)d_in[7];
    float* out = (float*)d_out;

    // Split hidden states into bf16 hi/lo
    int n4 = (Mtot * Dn) / 4;
    split_kernel<<<(n4 + 255) / 256, 256>>>(hs, g_hs_hi, g_hs_lo, n4);

    dim3 tgrid(32, 32), tblk(32, 32);
    dim3 ggrid(Dn / 128, Mtot / 128);   // (8, 64)

    splitT_kernel<<<tgrid, tblk>>>(Wq, g_wt_hi, g_wt_lo);
    qkv_gemm_mma<<<ggrid, 256>>>(g_hs_hi, g_hs_lo, g_wt_hi, g_wt_lo, bq, 0);

    splitT_kernel<<<tgrid, tblk>>>(Wk, g_wt_hi, g_wt_lo);
    qkv_gemm_mma<<<ggrid, 256>>>(g_hs_hi, g_hs_lo, g_wt_hi, g_wt_lo, bk, 1);

    splitT_kernel<<<tgrid, tblk>>>(Wv, g_wt_hi, g_wt_lo);
    qkv_gemm_mma<<<ggrid, 256>>>(g_hs_hi, g_hs_lo, g_wt_hi, g_wt_lo, bv, 2);

    dim3 attnGrid(Sn / 64, Bn * Hn);
    attn_kernel<<<attnGrid, 128>>>(mask, out);
}

// round 4
// speedup vs baseline: 5.6291x; 5.6291x over previous
#include <cuda_runtime.h>
#include <cstdint>

#define Bn 8
#define Sn 1024
#define Dn 1024
#define Hn 16
#define HDn 64
#define Mtot (Bn * Sn)   // 8192

// ---------------------------------------------------------------------------
// Scratch (__device__ globals; allocation-free rule)
// ---------------------------------------------------------------------------
__device__ float g_q[Bn * Hn * Sn * HDn];
__device__ float g_k[Bn * Hn * Sn * HDn];
__device__ float g_v[Bn * Hn * Sn * HDn];

// ---------------------------------------------------------------------------
// Packed f32x2 helpers (Blackwell sm_100+ base PTX)
// ---------------------------------------------------------------------------
__device__ __forceinline__ void fma2(uint64_t& d, uint64_t a, uint64_t b) {
    asm("fma.rn.f32x2 %0, %1, %2, %0;" : "+l"(d) : "l"(a), "l"(b));
}
__device__ __forceinline__ void mul2(uint64_t& d, uint64_t a) {
    asm("mul.rn.f32x2 %0, %0, %1;" : "+l"(d) : "l"(a));
}
__device__ __forceinline__ uint64_t pack2(float x) {
    uint64_t r;
    asm("mov.b64 %0, {%1, %1};" : "=l"(r) : "f"(x));
    return r;
}
__device__ __forceinline__ float2 unpack2(uint64_t v) {
    float lo, hi;
    asm("mov.b64 {%0, %1}, %2;" : "=f"(lo), "=f"(hi) : "l"(v));
    return make_float2(lo, hi);
}

// ---------------------------------------------------------------------------
// f32x2 SGEMM: out = A[8192x1024] @ W[1024x1024] + bias, scatter to [B,H,S,HD]
// BM=BN=128, BK=16, 256 threads, 8x8 per-thread microtile (4 n-pairs).
// A tile stored DUPLICATED in smem so {m,m} pairs are direct 64-bit loads.
// ---------------------------------------------------------------------------
__global__ __launch_bounds__(256) void qkv_gemm_kernel(
    const float* __restrict__ A, const float* __restrict__ W,
    const float* __restrict__ bias, int sel)
{
    constexpr int K = Dn;
    __shared__ float Asd[16][256];   // [k][2m] duplicated A, 16KB
    __shared__ float Bs[16][128];    // [k][n], 8KB

    float* out = (sel == 0) ? g_q : (sel == 1) ? g_k : g_v;

    const int tid = threadIdx.x;
    const int blockRow = blockIdx.y * 128;
    const int blockCol = blockIdx.x * 128;

    const int threadRow = (tid / 16) * 8;   // 0..120
    const int threadCol = (tid % 16) * 8;   // 0..120

    uint64_t acc2[8][4];
#pragma unroll
    for (int i = 0; i < 8; i++)
#pragma unroll
        for (int j = 0; j < 4; j++) acc2[i][j] = 0ull;

    for (int k0 = 0; k0 < K; k0 += 16) {
        // Load A tile (128x16, duplicated) and B tile (16x128)
#pragma unroll
        for (int it = 0; it < 2; it++) {
            int lin = tid + it * 256;              // 0..511
            int ra = lin >> 2;                     // 0..127
            int ca = (lin & 3) << 2;               // 0,4,8,12
            float4 av = *(const float4*)(A + (size_t)(blockRow + ra) * K + k0 + ca);
            *(float2*)&Asd[ca + 0][2 * ra] = make_float2(av.x, av.x);
            *(float2*)&Asd[ca + 1][2 * ra] = make_float2(av.y, av.y);
            *(float2*)&Asd[ca + 2][2 * ra] = make_float2(av.z, av.z);
            *(float2*)&Asd[ca + 3][2 * ra] = make_float2(av.w, av.w);

            int rb = lin >> 5;                     // 0..15
            int cb = (lin & 31) << 2;              // 0..124
            *(float4*)&Bs[rb][cb] =
                *(const float4*)(W + (size_t)(k0 + rb) * Dn + blockCol + cb);
        }
        __syncthreads();

#pragma unroll
        for (int kk = 0; kk < 16; kk++) {
            ulonglong2 m0 = *(const ulonglong2*)&Asd[kk][2 * threadRow];
            ulonglong2 m1 = *(const ulonglong2*)&Asd[kk][2 * threadRow + 4];
            ulonglong2 m2 = *(const ulonglong2*)&Asd[kk][2 * threadRow + 8];
            ulonglong2 m3 = *(const ulonglong2*)&Asd[kk][2 * threadRow + 12];
            ulonglong2 n0 = *(const ulonglong2*)&Bs[kk][threadCol];
            ulonglong2 n1 = *(const ulonglong2*)&Bs[kk][threadCol + 4];
            uint64_t M[8] = {m0.x, m0.y, m1.x, m1.y, m2.x, m2.y, m3.x, m3.y};
            uint64_t N[4] = {n0.x, n0.y, n1.x, n1.y};
#pragma unroll
            for (int i = 0; i < 8; i++)
#pragma unroll
                for (int j = 0; j < 4; j++)
                    fma2(acc2[i][j], M[i], N[j]);
        }
        __syncthreads();
    }

    // Epilogue: bias + scatter to [B,H,S,HD]
#pragma unroll
    for (int i = 0; i < 8; i++) {
        int m = blockRow + threadRow + i;
        int b = m >> 10;
        int s = m & 1023;
#pragma unroll
        for (int jp = 0; jp < 2; jp++) {
            int n = blockCol + threadCol + jp * 4;
            int h = n >> 6;
            int hd = n & 63;
            float2 p0 = unpack2(acc2[i][2 * jp]);
            float2 p1 = unpack2(acc2[i][2 * jp + 1]);
            float4 bv = *(const float4*)(bias + n);
            float4 v;
            v.x = p0.x + bv.x;
            v.y = p0.y + bv.y;
            v.z = p1.x + bv.z;
            v.w = p1.y + bv.w;
            *(float4*)(out + (((size_t)(b * Hn + h) * Sn + s) * HDn) + hd) = v;
        }
    }
}

// ---------------------------------------------------------------------------
// Flash-style attention with f32x2 math: grid (S/64, B*H), 128 threads.
// QK: k-paired FMA2 (natural pairs both sides) + horizontal add.
// PV: d-paired FMA2, {p,p} packed in regs, alpha rescale via mul.f32x2.
// ---------------------------------------------------------------------------
__global__ __launch_bounds__(128) void attn_kernel(
    const float* __restrict__ mask, float* __restrict__ out)
{
    __shared__ float Qs[64][68];
    __shared__ float Ks[32][64];
    __shared__ float Vs[32][64];
    __shared__ float Ps[64][33];
    __shared__ float mrow[64], lrow[64], arow[64];

    const int tid = threadIdx.x;
    const int qt = blockIdx.x;
    const int bh = blockIdx.y;
    const int b = bh >> 4;

    const float* Qg = g_q + (size_t)bh * Sn * HDn + (size_t)qt * 64 * HDn;
    const float* Kg = g_k + (size_t)bh * Sn * HDn;
    const float* Vg = g_v + (size_t)bh * Sn * HDn;

    const int r = tid & 63;
    const int half = tid >> 6;
    const int csBase = half * 16;
    const int cdBase = half * 32;

#pragma unroll
    for (int i = 0; i < 8; i++) {
        int lin = tid + i * 128;
        int row = lin >> 4;
        int c4 = (lin & 15) << 2;
        *(float4*)&Qs[row][c4] = *(const float4*)(Qg + row * HDn + c4);
    }
    if (tid < 64) { mrow[tid] = -1e30f; lrow[tid] = 0.f; }

    uint64_t acc2[16];
#pragma unroll
    for (int d = 0; d < 16; d++) acc2[d] = 0ull;
    __syncthreads();

    for (int kt = 0; kt < Sn / 32; kt++) {
#pragma unroll
        for (int i = 0; i < 4; i++) {
            int lin = tid + i * 128;
            int row = lin >> 4;
            int c4 = (lin & 15) << 2;
            *(float4*)&Ks[row][c4] = *(const float4*)(Kg + (size_t)kt * 32 * HDn + row * HDn + c4);
            *(float4*)&Vs[row][c4] = *(const float4*)(Vg + (size_t)kt * 32 * HDn + row * HDn + c4);
        }
        __syncthreads();

        // ---- QK: 16 score columns per thread, k-paired FMA2 ----
        uint64_t s2[16];
#pragma unroll
        for (int j = 0; j < 16; j++) s2[j] = 0ull;
#pragma unroll
        for (int kc = 0; kc < 8; kc++) {   // chunks of 8 k (4 pairs)
            const float* qp = &Qs[r][kc * 8];
            uint64_t q0 = *(const uint64_t*)(qp + 0);
            uint64_t q1 = *(const uint64_t*)(qp + 2);
            uint64_t q2 = *(const uint64_t*)(qp + 4);
            uint64_t q3 = *(const uint64_t*)(qp + 6);
#pragma unroll
            for (int j = 0; j < 16; j++) {
                const float* kp = &Ks[csBase + j][kc * 8];
                ulonglong2 ka = *(const ulonglong2*)(kp);
                ulonglong2 kb = *(const ulonglong2*)(kp + 4);
                fma2(s2[j], q0, ka.x);
                fma2(s2[j], q1, ka.y);
                fma2(s2[j], q2, kb.x);
                fma2(s2[j], q3, kb.y);
            }
        }
        const float scale = 0.125f;   // 1/sqrt(64)
#pragma unroll
        for (int j = 0; j < 16; j++) {
            float2 f = unpack2(s2[j]);
            int col = csBase + j;
            Ps[r][col] = (f.x + f.y) * scale + mask[b * Sn + kt * 32 + col];
        }
        __syncthreads();

        // ---- online softmax (one thread per row) ----
        if (tid < 64) {
            float mold = mrow[tid];
            float mt = mold;
#pragma unroll 8
            for (int j = 0; j < 32; j++) mt = fmaxf(mt, Ps[tid][j]);
            float a = __expf(mold - mt);
            float sum = 0.f;
#pragma unroll 8
            for (int j = 0; j < 32; j++) {
                float p = __expf(Ps[tid][j] - mt);
                Ps[tid][j] = p;
                sum += p;
            }
            lrow[tid] = lrow[tid] * a + sum;
            mrow[tid] = mt;
            arow[tid] = a;
        }
        __syncthreads();

        // ---- PV: d-paired FMA2, 32 dims per thread ----
        uint64_t a2 = pack2(arow[r]);
#pragma unroll
        for (int d = 0; d < 16; d++) mul2(acc2[d], a2);
#pragma unroll 4
        for (int j = 0; j < 32; j++) {
            uint64_t p2 = pack2(Ps[r][j]);
            const float* vp = &Vs[j][cdBase];
#pragma unroll
            for (int q = 0; q < 8; q++) {
                ulonglong2 v = *(const ulonglong2*)(vp + q * 4);
                fma2(acc2[q * 2 + 0], p2, v.x);
                fma2(acc2[q * 2 + 1], p2, v.y);
            }
        }
        __syncthreads();
    }

    // Final normalize + scatter to [B,S,D]
    const float inv = 1.f / lrow[r];
    const int qglob = qt * 64 + r;
    const int h = bh & 15;
    float* op = out + ((size_t)b * Sn + qglob) * Dn + h * HDn + cdBase;
#pragma unroll
    for (int q = 0; q < 8; q++) {
        float2 p0 = unpack2(acc2[q * 2 + 0]);
        float2 p1 = unpack2(acc2[q * 2 + 1]);
        float4 v;
        v.x = p0.x * inv;
        v.y = p0.y * inv;
        v.z = p1.x * inv;
        v.w = p1.y * inv;
        *(float4*)(op + q * 4) = v;
    }
}

// ---------------------------------------------------------------------------
// Launch
// ---------------------------------------------------------------------------
extern "C" void kernel_launch(void* const* d_in, const int* in_sizes, int n_in,
                              void* d_out, int out_size)
{
    const float* hs   = (const float*)d_in[0];
    const float* mask = (const float*)d_in[1];
    const float* Wq   = (const float*)d_in[2];
    const float* bq   = (const float*)d_in[3];
    const float* Wk   = (const float*)d_in[4];
    const float* bk   = (const float*)d_in[5];
    const float* Wv   = (const float*)d_in[6];
    const float* bv   = (const float*)d_in[7];
    float* out = (float*)d_out;

    dim3 gemmGrid(Dn / 128, Mtot / 128);   // (8, 64)
    qkv_gemm_kernel<<<gemmGrid, 256>>>(hs, Wq, bq, 0);
    qkv_gemm_kernel<<<gemmGrid, 256>>>(hs, Wk, bk, 1);
    qkv_gemm_kernel<<<gemmGrid, 256>>>(hs, Wv, bv, 2);

    dim3 attnGrid(Sn / 64, Bn * Hn);       // (16, 128)
    attn_kernel<<<attnGrid, 128>>>(mask, out);
}

// round 5
// speedup vs baseline: 6.6282x; 1.1775x over previous
#include <cuda_runtime.h>
#include <cstdint>

#define Bn 8
#define Sn 1024
#define Dn 1024
#define Hn 16
#define HDn 64
#define Mtot (Bn * Sn)   // 8192

// ---------------------------------------------------------------------------
// Scratch (__device__ globals; allocation-free rule)
// ---------------------------------------------------------------------------
__device__ float g_q[Bn * Hn * Sn * HDn];
__device__ float g_k[Bn * Hn * Sn * HDn];
__device__ float g_v[Bn * Hn * Sn * HDn];

// ---------------------------------------------------------------------------
// Packed f32x2 helpers
// ---------------------------------------------------------------------------
__device__ __forceinline__ void fma2(uint64_t& d, uint64_t a, uint64_t b) {
    asm("fma.rn.f32x2 %0, %1, %2, %0;" : "+l"(d) : "l"(a), "l"(b));
}
__device__ __forceinline__ void mul2(uint64_t& d, uint64_t a) {
    asm("mul.rn.f32x2 %0, %0, %1;" : "+l"(d) : "l"(a));
}
__device__ __forceinline__ uint64_t pack2(float x) {
    uint64_t r;
    asm("mov.b64 %0, {%1, %1};" : "=l"(r) : "f"(x));
    return r;
}
__device__ __forceinline__ float2 unpack2(uint64_t v) {
    float lo, hi;
    asm("mov.b64 {%0, %1}, %2;" : "=f"(lo), "=f"(hi) : "l"(v));
    return make_float2(lo, hi);
}

// ---------------------------------------------------------------------------
// GEMM: out = A[8192x1024] @ W[1024x1024] + bias, scatter to [B,H,S,HD].
// R1 smem layout (As transposed, Bs row-major), fma2 math:
// B-pairs are native contiguous pairs; A broadcast packed in registers.
// ---------------------------------------------------------------------------
__global__ __launch_bounds__(256) void qkv_gemm_kernel(
    const float* __restrict__ A, const float* __restrict__ W,
    const float* __restrict__ bias, int sel)
{
    constexpr int K = Dn;
    __shared__ float As[16][128];   // [k][m]
    __shared__ float Bs[16][128];   // [k][n]

    float* out = (sel == 0) ? g_q : (sel == 1) ? g_k : g_v;

    const int tid = threadIdx.x;
    const int blockRow = blockIdx.y * 128;
    const int blockCol = blockIdx.x * 128;

    const int threadRow = (tid / 16) * 8;
    const int threadCol = (tid % 16) * 8;

    uint64_t acc2[8][4];
#pragma unroll
    for (int i = 0; i < 8; i++)
#pragma unroll
        for (int j = 0; j < 4; j++) acc2[i][j] = 0ull;

    for (int k0 = 0; k0 < K; k0 += 16) {
#pragma unroll
        for (int it = 0; it < 2; it++) {
            int lin = tid + it * 256;
            int ra = lin >> 2;
            int ca = (lin & 3) << 2;
            float4 av = *(const float4*)(A + (size_t)(blockRow + ra) * K + k0 + ca);
            As[ca + 0][ra] = av.x;
            As[ca + 1][ra] = av.y;
            As[ca + 2][ra] = av.z;
            As[ca + 3][ra] = av.w;

            int rb = lin >> 5;
            int cb = (lin & 31) << 2;
            *(float4*)&Bs[rb][cb] =
                *(const float4*)(W + (size_t)(k0 + rb) * Dn + blockCol + cb);
        }
        __syncthreads();

#pragma unroll
        for (int kk = 0; kk < 16; kk++) {
            float4 a0 = *(const float4*)&As[kk][threadRow];
            float4 a1 = *(const float4*)&As[kk][threadRow + 4];
            ulonglong2 nA = *(const ulonglong2*)&Bs[kk][threadCol];
            ulonglong2 nB = *(const ulonglong2*)&Bs[kk][threadCol + 4];
            uint64_t N[4] = {nA.x, nA.y, nB.x, nB.y};
            float Ms[8] = {a0.x, a0.y, a0.z, a0.w, a1.x, a1.y, a1.z, a1.w};
#pragma unroll
            for (int i = 0; i < 8; i++) {
                uint64_t m2 = pack2(Ms[i]);
#pragma unroll
                for (int j = 0; j < 4; j++) fma2(acc2[i][j], m2, N[j]);
            }
        }
        __syncthreads();
    }

    // Epilogue: bias + scatter to [B,H,S,HD]
#pragma unroll
    for (int i = 0; i < 8; i++) {
        int m = blockRow + threadRow + i;
        int b = m >> 10;
        int s = m & 1023;
#pragma unroll
        for (int jp = 0; jp < 2; jp++) {
            int n = blockCol + threadCol + jp * 4;
            int h = n >> 6;
            int hd = n & 63;
            float2 p0 = unpack2(acc2[i][2 * jp]);
            float2 p1 = unpack2(acc2[i][2 * jp + 1]);
            float4 bv = *(const float4*)(bias + n);
            float4 v;
            v.x = p0.x + bv.x;
            v.y = p0.y + bv.y;
            v.z = p1.x + bv.z;
            v.w = p1.y + bv.w;
            *(float4*)(out + (((size_t)(b * Hn + h) * Sn + s) * HDn) + hd) = v;
        }
    }
}

// ---------------------------------------------------------------------------
// Flash attention, microtiled. grid (S/64, B*H), 128 threads, dyn smem ~69KB.
// Per iteration: 64 q x 64 keys. QK: 4q x 8k per thread (cyclic rows),
// fma2 over k-dim pairs. PV: 4q x 8d per thread, fma2 over d pairs.
// Two-phase parallel online softmax.
// Strides: Qs/Ks/Vs 68 floats (LDS.64/128-aligned, conflict-free);
// PsT transposed [k][q], stride 66.
// ---------------------------------------------------------------------------
#define QS_OFF 0
#define KS_OFF (64 * 68)
#define VS_OFF (2 * 64 * 68)
#define PS_OFF (3 * 64 * 68)            // PsT[64][66]
#define MR_OFF (PS_OFF + 64 * 66)
#define LR_OFF (MR_OFF + 64)
#define AR_OFF (LR_OFF + 64)
#define PM_OFF (AR_OFF + 64)            // pmax[128]
#define SU_OFF (PM_OFF + 128)           // psum[128]
#define ATTN_SMEM ((SU_OFF + 128) * 4)  // bytes = 70912

__global__ void attn_kernel(const float* __restrict__ mask,
                            float* __restrict__ out)
{
    extern __shared__ float sm[];
    float* Qs  = sm + QS_OFF;   // [64][68]
    float* Ks  = sm + KS_OFF;   // [64][68]
    float* Vs  = sm + VS_OFF;   // [64][68]
    float* PsT = sm + PS_OFF;   // [64 k][66 q]
    float* mrow = sm + MR_OFF;
    float* lrow = sm + LR_OFF;
    float* arow = sm + AR_OFF;
    float* pmax = sm + PM_OFF;
    float* psum = sm + SU_OFF;

    const int tid = threadIdx.x;
    const int qt = blockIdx.x;
    const int bh = blockIdx.y;
    const int bix = bh >> 4;

    const float* Qg = g_q + (size_t)bh * Sn * HDn + (size_t)qt * 64 * HDn;
    const float* Kg = g_k + (size_t)bh * Sn * HDn;
    const float* Vg = g_v + (size_t)bh * Sn * HDn;

    const int tq = tid >> 3;   // 0..15: q rows {tq, tq+16, tq+32, tq+48}
    const int tk = tid & 7;    // 0..7 : k cols {tk + 8b} / d cols td*8..

    // Load Q tile (64x64)
#pragma unroll
    for (int i = 0; i < 8; i++) {
        int lin = tid + i * 128;
        int row = lin >> 4;
        int c4 = (lin & 15) << 2;
        *(float4*)&Qs[row * 68 + c4] = *(const float4*)(Qg + row * HDn + c4);
    }
    if (tid < 64) { mrow[tid] = -1e30f; lrow[tid] = 0.f; }

    uint64_t ctx2[16];   // [a][dp]: q = tq+16a, d pair = tk*8 + 2dp
#pragma unroll
    for (int i = 0; i < 16; i++) ctx2[i] = 0ull;
    __syncthreads();

    for (int kt = 0; kt < Sn / 64; kt++) {
        // Load K,V tiles (64x64 each)
#pragma unroll
        for (int i = 0; i < 8; i++) {
            int lin = tid + i * 128;
            int row = lin >> 4;
            int c4 = (lin & 15) << 2;
            const float* kr = Kg + (size_t)kt * 64 * HDn + row * HDn + c4;
            const float* vr = Vg + (size_t)kt * 64 * HDn + row * HDn + c4;
            *(float4*)&Ks[row * 68 + c4] = *(const float4*)kr;
            *(float4*)&Vs[row * 68 + c4] = *(const float4*)vr;
        }
        __syncthreads();

        // ---- QK: 4q x 8k scores per thread, fma2 over k-dim pairs ----
        {
            uint64_t s2[4][8];
#pragma unroll
            for (int a = 0; a < 4; a++)
#pragma unroll
                for (int bb = 0; bb < 8; bb++) s2[a][bb] = 0ull;

#pragma unroll 4
            for (int kp = 0; kp < 32; kp++) {
                uint64_t q2[4], k2[8];
#pragma unroll
                for (int a = 0; a < 4; a++)
                    q2[a] = *(const uint64_t*)&Qs[(tq + 16 * a) * 68 + 2 * kp];
#pragma unroll
                for (int bb = 0; bb < 8; bb++)
                    k2[bb] = *(const uint64_t*)&Ks[(tk + 8 * bb) * 68 + 2 * kp];
#pragma unroll
                for (int a = 0; a < 4; a++)
#pragma unroll
                    for (int bb = 0; bb < 8; bb++)
                        fma2(s2[a][bb], q2[a], k2[bb]);
            }

            const float scale = 0.125f;   // 1/sqrt(64)
#pragma unroll
            for (int bb = 0; bb < 8; bb++) {
                const int kcol = tk + 8 * bb;
                const float mv = mask[bix * Sn + kt * 64 + kcol];
#pragma unroll
                for (int a = 0; a < 4; a++) {
                    float2 f = unpack2(s2[a][bb]);
                    PsT[kcol * 66 + (tq + 16 * a)] = (f.x + f.y) * scale + mv;
                }
            }
        }
        __syncthreads();

        // ---- softmax, two-phase parallel over 128 threads ----
        {
            const int r = tid & 63;
            const int ch = (tid >> 6) * 32;
            float lm = -1e30f;
#pragma unroll 8
            for (int j = 0; j < 32; j++) lm = fmaxf(lm, PsT[(ch + j) * 66 + r]);
            pmax[tid] = lm;
            __syncthreads();

            if (tid < 64) {
                float mt = fmaxf(mrow[tid], fmaxf(pmax[tid], pmax[tid + 64]));
                arow[tid] = __expf(mrow[tid] - mt);
                mrow[tid] = mt;
                pmax[tid] = mt;
            }
            __syncthreads();

            const float mt = pmax[r];
            float s = 0.f;
#pragma unroll 8
            for (int j = 0; j < 32; j++) {
                float p = __expf(PsT[(ch + j) * 66 + r] - mt);
                PsT[(ch + j) * 66 + r] = p;
                s += p;
            }
            psum[tid] = s;
            __syncthreads();

            if (tid < 64)
                lrow[tid] = lrow[tid] * arow[tid] + psum[tid] + psum[tid + 64];
        }
        __syncthreads();

        // ---- PV: 4q x 8d per thread, fma2 over d pairs ----
        {
            const int td = tk;           // d block = td*8
#pragma unroll
            for (int a = 0; a < 4; a++) {
                uint64_t a2 = pack2(arow[tq + 16 * a]);
#pragma unroll
                for (int dp = 0; dp < 4; dp++) mul2(ctx2[a * 4 + dp], a2);
            }
#pragma unroll 4
            for (int j = 0; j < 64; j++) {
                ulonglong2 v01 = *(const ulonglong2*)&Vs[j * 68 + td * 8];
                ulonglong2 v23 = *(const ulonglong2*)&Vs[j * 68 + td * 8 + 4];
#pragma unroll
                for (int a = 0; a < 4; a++) {
                    uint64_t p2 = pack2(PsT[j * 66 + (tq + 16 * a)]);
                    fma2(ctx2[a * 4 + 0], p2, v01.x);
                    fma2(ctx2[a * 4 + 1], p2, v01.y);
                    fma2(ctx2[a * 4 + 2], p2, v23.x);
                    fma2(ctx2[a * 4 + 3], p2, v23.y);
                }
            }
        }
        __syncthreads();
    }

    // Final normalize + scatter to [B,S,D]
    const int h = bh & 15;
    const int td = tk;
#pragma unroll
    for (int a = 0; a < 4; a++) {
        const int q = tq + 16 * a;
        const float inv = 1.f / lrow[q];
        const int qglob = qt * 64 + q;
        float* op = out + ((size_t)bix * Sn + qglob) * Dn + h * HDn + td * 8;
        float2 c0 = unpack2(ctx2[a * 4 + 0]);
        float2 c1 = unpack2(ctx2[a * 4 + 1]);
        float2 c2 = unpack2(ctx2[a * 4 + 2]);
        float2 c3 = unpack2(ctx2[a * 4 + 3]);
        float4 v0 = make_float4(c0.x * inv, c0.y * inv, c1.x * inv, c1.y * inv);
        float4 v1 = make_float4(c2.x * inv, c2.y * inv, c3.x * inv, c3.y * inv);
        *(float4*)(op) = v0;
        *(float4*)(op + 4) = v1;
    }
}

// ---------------------------------------------------------------------------
// Launch
// ---------------------------------------------------------------------------
extern "C" void kernel_launch(void* const* d_in, const int* in_sizes, int n_in,
                              void* d_out, int out_size)
{
    const float* hs   = (const float*)d_in[0];
    const float* mask = (const float*)d_in[1];
    const float* Wq   = (const float*)d_in[2];
    const float* bq   = (const float*)d_in[3];
    const float* Wk   = (const float*)d_in[4];
    const float* bk   = (const float*)d_in[5];
    const float* Wv   = (const float*)d_in[6];
    const float* bv   = (const float*)d_in[7];
    float* out = (float*)d_out;

    // Idempotent, deterministic, CPU-side: safe on every call.
    cudaFuncSetAttribute(attn_kernel,
                         cudaFuncAttributeMaxDynamicSharedMemorySize, ATTN_SMEM);

    dim3 gemmGrid(Dn / 128, Mtot / 128);   // (8, 64)
    qkv_gemm_kernel<<<gemmGrid, 256>>>(hs, Wq, bq, 0);
    qkv_gemm_kernel<<<gemmGrid, 256>>>(hs, Wk, bk, 1);
    qkv_gemm_kernel<<<gemmGrid, 256>>>(hs, Wv, bv, 2);

    dim3 attnGrid(Sn / 64, Bn * Hn);       // (16, 128)
    attn_kernel<<<attnGrid, 128, ATTN_SMEM>>>(mask, out);
}

// round 6
// speedup vs baseline: 6.8303x; 1.0305x over previous
#include <cuda_runtime.h>
#include <cstdint>

#define Bn 8
#define Sn 1024
#define Dn 1024
#define Hn 16
#define HDn 64
#define Mtot (Bn * Sn)   // 8192

// ---------------------------------------------------------------------------
// Scratch (__device__ globals; allocation-free rule)
// ---------------------------------------------------------------------------
__device__ float g_q[Bn * Hn * Sn * HDn];
__device__ float g_k[Bn * Hn * Sn * HDn];
__device__ float g_v[Bn * Hn * Sn * HDn];

// ---------------------------------------------------------------------------
// Packed f32x2 helpers
// ---------------------------------------------------------------------------
__device__ __forceinline__ void fma2(uint64_t& d, uint64_t a, uint64_t b) {
    asm("fma.rn.f32x2 %0, %1, %2, %0;" : "+l"(d) : "l"(a), "l"(b));
}
__device__ __forceinline__ void mul2(uint64_t& d, uint64_t a) {
    asm("mul.rn.f32x2 %0, %0, %1;" : "+l"(d) : "l"(a));
}
__device__ __forceinline__ uint64_t pack2(float x) {
    uint64_t r;
    asm("mov.b64 %0, {%1, %1};" : "=l"(r) : "f"(x));
    return r;
}
__device__ __forceinline__ float2 unpack2(uint64_t v) {
    float lo, hi;
    asm("mov.b64 {%0, %1}, %2;" : "=f"(lo), "=f"(hi) : "l"(v));
    return make_float2(lo, hi);
}

// ---------------------------------------------------------------------------
// GEMM (unchanged from R5 — measured at the fp32 pipe floor).
// ---------------------------------------------------------------------------
__global__ __launch_bounds__(256) void qkv_gemm_kernel(
    const float* __restrict__ A, const float* __restrict__ W,
    const float* __restrict__ bias, int sel)
{
    constexpr int K = Dn;
    __shared__ float As[16][128];   // [k][m]
    __shared__ float Bs[16][128];   // [k][n]

    float* out = (sel == 0) ? g_q : (sel == 1) ? g_k : g_v;

    const int tid = threadIdx.x;
    const int blockRow = blockIdx.y * 128;
    const int blockCol = blockIdx.x * 128;

    const int threadRow = (tid / 16) * 8;
    const int threadCol = (tid % 16) * 8;

    uint64_t acc2[8][4];
#pragma unroll
    for (int i = 0; i < 8; i++)
#pragma unroll
        for (int j = 0; j < 4; j++) acc2[i][j] = 0ull;

    for (int k0 = 0; k0 < K; k0 += 16) {
#pragma unroll
        for (int it = 0; it < 2; it++) {
            int lin = tid + it * 256;
            int ra = lin >> 2;
            int ca = (lin & 3) << 2;
            float4 av = *(const float4*)(A + (size_t)(blockRow + ra) * K + k0 + ca);
            As[ca + 0][ra] = av.x;
            As[ca + 1][ra] = av.y;
            As[ca + 2][ra] = av.z;
            As[ca + 3][ra] = av.w;

            int rb = lin >> 5;
            int cb = (lin & 31) << 2;
            *(float4*)&Bs[rb][cb] =
                *(const float4*)(W + (size_t)(k0 + rb) * Dn + blockCol + cb);
        }
        __syncthreads();

#pragma unroll
        for (int kk = 0; kk < 16; kk++) {
            float4 a0 = *(const float4*)&As[kk][threadRow];
            float4 a1 = *(const float4*)&As[kk][threadRow + 4];
            ulonglong2 nA = *(const ulonglong2*)&Bs[kk][threadCol];
            ulonglong2 nB = *(const ulonglong2*)&Bs[kk][threadCol + 4];
            uint64_t N[4] = {nA.x, nA.y, nB.x, nB.y};
            float Ms[8] = {a0.x, a0.y, a0.z, a0.w, a1.x, a1.y, a1.z, a1.w};
#pragma unroll
            for (int i = 0; i < 8; i++) {
                uint64_t m2 = pack2(Ms[i]);
#pragma unroll
                for (int j = 0; j < 4; j++) fma2(acc2[i][j], m2, N[j]);
            }
        }
        __syncthreads();
    }

#pragma unroll
    for (int i = 0; i < 8; i++) {
        int m = blockRow + threadRow + i;
        int b = m >> 10;
        int s = m & 1023;
#pragma unroll
        for (int jp = 0; jp < 2; jp++) {
            int n = blockCol + threadCol + jp * 4;
            int h = n >> 6;
            int hd = n & 63;
            float2 p0 = unpack2(acc2[i][2 * jp]);
            float2 p1 = unpack2(acc2[i][2 * jp + 1]);
            float4 bv = *(const float4*)(bias + n);
            float4 v;
            v.x = p0.x + bv.x;
            v.y = p0.y + bv.y;
            v.z = p1.x + bv.z;
            v.w = p1.y + bv.w;
            *(float4*)(out + (((size_t)(b * Hn + h) * Sn + s) * HDn) + hd) = v;
        }
    }
}

// ---------------------------------------------------------------------------
// Flash attention v3. grid (S/64, B*H), 128 threads.
// 64q x 64k per iteration. Thread (tq=tid>>3, tk=tid&7):
//   q rows = 4*tq .. 4*tq+3 (block assignment, bank-distinct)
//   QK: 4q x 8k scores, LDS.128 fragments both sides, fma2 over dim pairs.
//   Ps stored [q][k] stride 68 -> softmax & PV use float4/LDS.128.
//   PV: 4q x 8d, V rows via LDS.128, p packed from float4 loads.
// ---------------------------------------------------------------------------
#define QS_OFF 0
#define KS_OFF (64 * 68)
#define VS_OFF (2 * 64 * 68)
#define PS_OFF (3 * 64 * 68)            // Ps[64 q][68]
#define MR_OFF (PS_OFF + 64 * 68)
#define LR_OFF (MR_OFF + 64)
#define AR_OFF (LR_OFF + 64)
#define PM_OFF (AR_OFF + 64)            // pmax[128]
#define SU_OFF (PM_OFF + 128)           // psum[128]
#define ATTN_SMEM ((SU_OFF + 128) * 4)  // 71424 bytes

__global__ void attn_kernel(const float* __restrict__ mask,
                            float* __restrict__ out)
{
    extern __shared__ float sm[];
    float* Qs  = sm + QS_OFF;
    float* Ks  = sm + KS_OFF;
    float* Vs  = sm + VS_OFF;
    float* Ps  = sm + PS_OFF;
    float* mrow = sm + MR_OFF;
    float* lrow = sm + LR_OFF;
    float* arow = sm + AR_OFF;
    float* pmax = sm + PM_OFF;
    float* psum = sm + SU_OFF;

    const int tid = threadIdx.x;
    const int qt = blockIdx.x;
    const int bh = blockIdx.y;
    const int bix = bh >> 4;

    const float* Qg = g_q + (size_t)bh * Sn * HDn + (size_t)qt * 64 * HDn;
    const float* Kg = g_k + (size_t)bh * Sn * HDn;
    const float* Vg = g_v + (size_t)bh * Sn * HDn;

    const int tq = tid >> 3;   // q rows 4tq..4tq+3
    const int tk = tid & 7;    // k cols tk+8b / d block tk*8

    // Load Q tile (64x64)
#pragma unroll
    for (int i = 0; i < 8; i++) {
        int lin = tid + i * 128;
        int row = lin >> 4;
        int c4 = (lin & 15) << 2;
        *(float4*)&Qs[row * 68 + c4] = *(const float4*)(Qg + row * HDn + c4);
    }
    if (tid < 64) { mrow[tid] = -1e30f; lrow[tid] = 0.f; }

    uint64_t ctx2[16];   // [a][dp]
#pragma unroll
    for (int i = 0; i < 16; i++) ctx2[i] = 0ull;
    __syncthreads();

    for (int kt = 0; kt < Sn / 64; kt++) {
        // Load K,V tiles
#pragma unroll
        for (int i = 0; i < 8; i++) {
            int lin = tid + i * 128;
            int row = lin >> 4;
            int c4 = (lin & 15) << 2;
            const float* kr = Kg + (size_t)kt * 64 * HDn + row * HDn + c4;
            const float* vr = Vg + (size_t)kt * 64 * HDn + row * HDn + c4;
            *(float4*)&Ks[row * 68 + c4] = *(const float4*)kr;
            *(float4*)&Vs[row * 68 + c4] = *(const float4*)vr;
        }
        __syncthreads();

        // ---- QK: 4q x 8k, LDS.128 fragments, fma2 over dim pairs ----
        {
            uint64_t s2[4][8];
#pragma unroll
            for (int a = 0; a < 4; a++)
#pragma unroll
                for (int bb = 0; bb < 8; bb++) s2[a][bb] = 0ull;

#pragma unroll 2
            for (int kc = 0; kc < 16; kc++) {   // 4 dims per chunk
                ulonglong2 q4[4];
#pragma unroll
                for (int a = 0; a < 4; a++)
                    q4[a] = *(const ulonglong2*)&Qs[(4 * tq + a) * 68 + 4 * kc];
#pragma unroll
                for (int bg = 0; bg < 2; bg++) {   // two groups of 4 k-cols
                    ulonglong2 k4[4];
#pragma unroll
                    for (int bb = 0; bb < 4; bb++)
                        k4[bb] = *(const ulonglong2*)
                            &Ks[(tk + 8 * (bg * 4 + bb)) * 68 + 4 * kc];
#pragma unroll
                    for (int a = 0; a < 4; a++)
#pragma unroll
                        for (int bb = 0; bb < 4; bb++) {
                            fma2(s2[a][bg * 4 + bb], q4[a].x, k4[bb].x);
                            fma2(s2[a][bg * 4 + bb], q4[a].y, k4[bb].y);
                        }
                }
            }

            const float scale = 0.125f;   // 1/sqrt(64)
#pragma unroll
            for (int bb = 0; bb < 8; bb++) {
                const int kcol = tk + 8 * bb;
                const float mv = mask[bix * Sn + kt * 64 + kcol];
#pragma unroll
                for (int a = 0; a < 4; a++) {
                    float2 f = unpack2(s2[a][bb]);
                    Ps[(4 * tq + a) * 68 + kcol] = (f.x + f.y) * scale + mv;
                }
            }
        }
        __syncthreads();

        // ---- softmax, two-phase, float4 accesses ----
        {
            const int r = tid & 63;
            const int ch = (tid >> 6) * 32;
            float lm = -1e30f;
#pragma unroll
            for (int j4 = 0; j4 < 8; j4++) {
                float4 p = *(const float4*)&Ps[r * 68 + ch + 4 * j4];
                lm = fmaxf(lm, fmaxf(fmaxf(p.x, p.y), fmaxf(p.z, p.w)));
            }
            pmax[tid] = lm;
            __syncthreads();

            if (tid < 64) {
                float mt = fmaxf(mrow[tid], fmaxf(pmax[tid], pmax[tid + 64]));
                arow[tid] = __expf(mrow[tid] - mt);
                mrow[tid] = mt;
                pmax[tid] = mt;
            }
            __syncthreads();

            const float mt = pmax[r];
            float s = 0.f;
#pragma unroll
            for (int j4 = 0; j4 < 8; j4++) {
                float4 p = *(float4*)&Ps[r * 68 + ch + 4 * j4];
                p.x = __expf(p.x - mt);
                p.y = __expf(p.y - mt);
                p.z = __expf(p.z - mt);
                p.w = __expf(p.w - mt);
                s += (p.x + p.y) + (p.z + p.w);
                *(float4*)&Ps[r * 68 + ch + 4 * j4] = p;
            }
            psum[tid] = s;
            __syncthreads();

            if (tid < 64)
                lrow[tid] = lrow[tid] * arow[tid] + psum[tid] + psum[tid + 64];
        }
        __syncthreads();

        // ---- PV: 4q x 8d, float4 p-loads, LDS.128 V rows ----
        {
            const int td = tk;
#pragma unroll
            for (int a = 0; a < 4; a++) {
                uint64_t a2 = pack2(arow[4 * tq + a]);
#pragma unroll
                for (int dp = 0; dp < 4; dp++) mul2(ctx2[a * 4 + dp], a2);
            }
#pragma unroll 2
            for (int jc = 0; jc < 16; jc++) {   // 4 keys per chunk
                float4 pf[4];
#pragma unroll
                for (int a = 0; a < 4; a++)
                    pf[a] = *(const float4*)&Ps[(4 * tq + a) * 68 + 4 * jc];
#pragma unroll
                for (int j = 0; j < 4; j++) {
                    const float* vp = &Vs[(4 * jc + j) * 68 + td * 8];
                    ulonglong2 v01 = *(const ulonglong2*)(vp);
                    ulonglong2 v23 = *(const ulonglong2*)(vp + 4);
#pragma unroll
                    for (int a = 0; a < 4; a++) {
                        float pj = (j == 0) ? pf[a].x : (j == 1) ? pf[a].y
                                 : (j == 2) ? pf[a].z : pf[a].w;
                        uint64_t p2 = pack2(pj);
                        fma2(ctx2[a * 4 + 0], p2, v01.x);
                        fma2(ctx2[a * 4 + 1], p2, v01.y);
                        fma2(ctx2[a * 4 + 2], p2, v23.x);
                        fma2(ctx2[a * 4 + 3], p2, v23.y);
                    }
                }
            }
        }
        __syncthreads();
    }

    // Final normalize + scatter to [B,S,D]
    const int h = bh & 15;
    const int td = tk;
#pragma unroll
    for (int a = 0; a < 4; a++) {
        const int q = 4 * tq + a;
        const float inv = 1.f / lrow[q];
        const int qglob = qt * 64 + q;
        float* op = out + ((size_t)bix * Sn + qglob) * Dn + h * HDn + td * 8;
        float2 c0 = unpack2(ctx2[a * 4 + 0]);
        float2 c1 = unpack2(ctx2[a * 4 + 1]);
        float2 c2 = unpack2(ctx2[a * 4 + 2]);
        float2 c3 = unpack2(ctx2[a * 4 + 3]);
        float4 v0 = make_float4(c0.x * inv, c0.y * inv, c1.x * inv, c1.y * inv);
        float4 v1 = make_float4(c2.x * inv, c2.y * inv, c3.x * inv, c3.y * inv);
        *(float4*)(op) = v0;
        *(float4*)(op + 4) = v1;
    }
}

// ---------------------------------------------------------------------------
// Launch
// ---------------------------------------------------------------------------
extern "C" void kernel_launch(void* const* d_in, const int* in_sizes, int n_in,
                              void* d_out, int out_size)
{
    const float* hs   = (const float*)d_in[0];
    const float* mask = (const float*)d_in[1];
    const float* Wq   = (const float*)d_in[2];
    const float* bq   = (const float*)d_in[3];
    const float* Wk   = (const float*)d_in[4];
    const float* bk   = (const float*)d_in[5];
    const float* Wv   = (const float*)d_in[6];
    const float* bv   = (const float*)d_in[7];
    float* out = (float*)d_out;

    cudaFuncSetAttribute(attn_kernel,
                         cudaFuncAttributeMaxDynamicSharedMemorySize, ATTN_SMEM);

    dim3 gemmGrid(Dn / 128, Mtot / 128);   // (8, 64)
    qkv_gemm_kernel<<<gemmGrid, 256>>>(hs, Wq, bq, 0);
    qkv_gemm_kernel<<<gemmGrid, 256>>>(hs, Wk, bk, 1);
    qkv_gemm_kernel<<<gemmGrid, 256>>>(hs, Wv, bv, 2);

    dim3 attnGrid(Sn / 64, Bn * Hn);       // (16, 128)
    attn_kernel<<<attnGrid, 128, ATTN_SMEM>>>(mask, out);
}

// round 7
// speedup vs baseline: 7.0430x; 1.0311x over previous
#include <cuda_runtime.h>
#include <cstdint>

#define Bn 8
#define Sn 1024
#define Dn 1024
#define Hn 16
#define HDn 64
#define Mtot (Bn * Sn)   // 8192

// ---------------------------------------------------------------------------
// Scratch (__device__ globals; allocation-free rule)
// ---------------------------------------------------------------------------
__device__ float g_q[Bn * Hn * Sn * HDn];
__device__ float g_k[Bn * Hn * Sn * HDn];
__device__ float g_v[Bn * Hn * Sn * HDn];

// ---------------------------------------------------------------------------
// Packed f32x2 helpers
// ---------------------------------------------------------------------------
__device__ __forceinline__ void fma2(uint64_t& d, uint64_t a, uint64_t b) {
    asm("fma.rn.f32x2 %0, %1, %2, %0;" : "+l"(d) : "l"(a), "l"(b));
}
__device__ __forceinline__ void mul2(uint64_t& d, uint64_t a) {
    asm("mul.rn.f32x2 %0, %0, %1;" : "+l"(d) : "l"(a));
}
__device__ __forceinline__ uint64_t pack2(float x) {
    uint64_t r;
    asm("mov.b64 %0, {%1, %1};" : "=l"(r) : "f"(x));
    return r;
}
__device__ __forceinline__ float2 unpack2(uint64_t v) {
    float lo, hi;
    asm("mov.b64 {%0, %1}, %2;" : "=f"(lo), "=f"(hi) : "l"(v));
    return make_float2(lo, hi);
}

// ---------------------------------------------------------------------------
// GEMM (unchanged — measured at the fp32 pipe floor).
// ---------------------------------------------------------------------------
__global__ __launch_bounds__(256) void qkv_gemm_kernel(
    const float* __restrict__ A, const float* __restrict__ W,
    const float* __restrict__ bias, int sel)
{
    constexpr int K = Dn;
    __shared__ float As[16][128];
    __shared__ float Bs[16][128];

    float* out = (sel == 0) ? g_q : (sel == 1) ? g_k : g_v;

    const int tid = threadIdx.x;
    const int blockRow = blockIdx.y * 128;
    const int blockCol = blockIdx.x * 128;

    const int threadRow = (tid / 16) * 8;
    const int threadCol = (tid % 16) * 8;

    uint64_t acc2[8][4];
#pragma unroll
    for (int i = 0; i < 8; i++)
#pragma unroll
        for (int j = 0; j < 4; j++) acc2[i][j] = 0ull;

    for (int k0 = 0; k0 < K; k0 += 16) {
#pragma unroll
        for (int it = 0; it < 2; it++) {
            int lin = tid + it * 256;
            int ra = lin >> 2;
            int ca = (lin & 3) << 2;
            float4 av = *(const float4*)(A + (size_t)(blockRow + ra) * K + k0 + ca);
            As[ca + 0][ra] = av.x;
            As[ca + 1][ra] = av.y;
            As[ca + 2][ra] = av.z;
            As[ca + 3][ra] = av.w;

            int rb = lin >> 5;
            int cb = (lin & 31) << 2;
            *(float4*)&Bs[rb][cb] =
                *(const float4*)(W + (size_t)(k0 + rb) * Dn + blockCol + cb);
        }
        __syncthreads();

#pragma unroll
        for (int kk = 0; kk < 16; kk++) {
            float4 a0 = *(const float4*)&As[kk][threadRow];
            float4 a1 = *(const float4*)&As[kk][threadRow + 4];
            ulonglong2 nA = *(const ulonglong2*)&Bs[kk][threadCol];
            ulonglong2 nB = *(const ulonglong2*)&Bs[kk][threadCol + 4];
            uint64_t N[4] = {nA.x, nA.y, nB.x, nB.y};
            float Ms[8] = {a0.x, a0.y, a0.z, a0.w, a1.x, a1.y, a1.z, a1.w};
#pragma unroll
            for (int i = 0; i < 8; i++) {
                uint64_t m2 = pack2(Ms[i]);
#pragma unroll
                for (int j = 0; j < 4; j++) fma2(acc2[i][j], m2, N[j]);
            }
        }
        __syncthreads();
    }

#pragma unroll
    for (int i = 0; i < 8; i++) {
        int m = blockRow + threadRow + i;
        int b = m >> 10;
        int s = m & 1023;
#pragma unroll
        for (int jp = 0; jp < 2; jp++) {
            int n = blockCol + threadCol + jp * 4;
            int h = n >> 6;
            int hd = n & 63;
            float2 p0 = unpack2(acc2[i][2 * jp]);
            float2 p1 = unpack2(acc2[i][2 * jp + 1]);
            float4 bv = *(const float4*)(bias + n);
            float4 v;
            v.x = p0.x + bv.x;
            v.y = p0.y + bv.y;
            v.z = p1.x + bv.z;
            v.w = p1.y + bv.w;
            *(float4*)(out + (((size_t)(b * Hn + h) * Sn + s) * HDn) + hd) = v;
        }
    }
}

// ---------------------------------------------------------------------------
// Flash attention v4, GEMM-style 8x8 microtiles.
// grid (Sn/128, B*H) = (8, 128), 256 threads, ~168KB dyn smem, 1 block/SM.
// Per kt (8 iters): 128 q x 128 k.
//  QK: QsT[d][q], KsT[d][k]; thread (tqg,tkg) does 8q x 8k, pair over k.
//  Scores -> PsT[k][q'] with rotation q' = (q + 4*(k>>3)) & 127.
//  PV: thread (pqg,pdg,pkh) does 8q x 8d over half the keys; combine at end.
// ---------------------------------------------------------------------------
#define QST_OFF 0                       // [64][132]
#define KST_OFF 8448                    // [64][132]
#define VS_OFF  16896                   // [128][68]
#define PST_OFF 25600                   // [128][128] rotated
#define MR_OFF  41984
#define LR_OFF  (MR_OFF + 128)
#define AR_OFF  (LR_OFF + 128)
#define PM_OFF  (AR_OFF + 128)          // [256]
#define SU_OFF  (PM_OFF + 256)          // [256]
#define ATTN_SMEM ((SU_OFF + 256) * 4)  // 171520 bytes

__global__ __launch_bounds__(256) void attn_kernel(
    const float* __restrict__ mask, float* __restrict__ out)
{
    extern __shared__ float sm[];
    float* QsT = sm + QST_OFF;
    float* KsT = sm + KST_OFF;
    float* Vs  = sm + VS_OFF;
    float* PsT = sm + PST_OFF;
    float* mrow = sm + MR_OFF;
    float* lrow = sm + LR_OFF;
    float* arow = sm + AR_OFF;
    float* pmax = sm + PM_OFF;
    float* psum = sm + SU_OFF;

    const int tid = threadIdx.x;
    const int qt = blockIdx.x;
    const int bh = blockIdx.y;
    const int bix = bh >> 4;
    const int h = bh & 15;

    const float* Qg = g_q + (size_t)bh * Sn * HDn + (size_t)qt * 128 * HDn;
    const float* Kg = g_k + (size_t)bh * Sn * HDn;
    const float* Vg = g_v + (size_t)bh * Sn * HDn;

    // ---- QsT fill (once): transpose 128q x 64d -> [d][q] ----
#pragma unroll
    for (int i = 0; i < 4; i++) {
        int lin = tid + i * 256;
        int q = lin & 127;
        int db = (lin >> 7) * 8;
        float4 f0 = *(const float4*)(Qg + q * HDn + db);
        float4 f1 = *(const float4*)(Qg + q * HDn + db + 4);
        QsT[(db + 0) * 132 + q] = f0.x;
        QsT[(db + 1) * 132 + q] = f0.y;
        QsT[(db + 2) * 132 + q] = f0.z;
        QsT[(db + 3) * 132 + q] = f0.w;
        QsT[(db + 4) * 132 + q] = f1.x;
        QsT[(db + 5) * 132 + q] = f1.y;
        QsT[(db + 6) * 132 + q] = f1.z;
        QsT[(db + 7) * 132 + q] = f1.w;
    }
    if (tid < 128) { mrow[tid] = -1e30f; lrow[tid] = 0.f; }

    uint64_t ctx2[8][4];
#pragma unroll
    for (int a = 0; a < 8; a++)
#pragma unroll
        for (int dp = 0; dp < 4; dp++) ctx2[a][dp] = 0ull;

    const int tqg = tid >> 4, tkg = tid & 15;           // QK mapping
    const int pqg = tid >> 4, pdg = (tid >> 1) & 7, pkh = tid & 1;  // PV

    __syncthreads();

    for (int kt = 0; kt < Sn / 128; kt++) {
        // ---- KsT fill (transpose) + Vs fill (copy) ----
#pragma unroll
        for (int i = 0; i < 4; i++) {
            int lin = tid + i * 256;
            int k = lin & 127;
            int db = (lin >> 7) * 8;
            const float* kr = Kg + (size_t)(kt * 128 + k) * HDn + db;
            float4 f0 = *(const float4*)(kr);
            float4 f1 = *(const float4*)(kr + 4);
            KsT[(db + 0) * 132 + k] = f0.x;
            KsT[(db + 1) * 132 + k] = f0.y;
            KsT[(db + 2) * 132 + k] = f0.z;
            KsT[(db + 3) * 132 + k] = f0.w;
            KsT[(db + 4) * 132 + k] = f1.x;
            KsT[(db + 5) * 132 + k] = f1.y;
            KsT[(db + 6) * 132 + k] = f1.z;
            KsT[(db + 7) * 132 + k] = f1.w;

            int kv = lin >> 3;
            int dc = (lin & 7) * 8;
            const float* vr = Vg + (size_t)(kt * 128 + kv) * HDn + dc;
            *(float4*)&Vs[kv * 68 + dc] = *(const float4*)(vr);
            *(float4*)&Vs[kv * 68 + dc + 4] = *(const float4*)(vr + 4);
        }
        __syncthreads();

        // ---- QK: 8q x 8k per thread, pair over k ----
        {
            uint64_t s2[8][4];
#pragma unroll
            for (int a = 0; a < 8; a++)
#pragma unroll
                for (int j = 0; j < 4; j++) s2[a][j] = 0ull;

            const float* qbase = QsT + 8 * tqg;
            const float* kbase = KsT + 8 * tkg;
#pragma unroll 4
            for (int d = 0; d < 64; d++) {
                float4 q0 = *(const float4*)(qbase + d * 132);
                float4 q1 = *(const float4*)(qbase + d * 132 + 4);
                ulonglong2 kA = *(const ulonglong2*)(kbase + d * 132);
                ulonglong2 kB = *(const ulonglong2*)(kbase + d * 132 + 4);
                uint64_t N[4] = {kA.x, kA.y, kB.x, kB.y};
                float qa[8] = {q0.x, q0.y, q0.z, q0.w, q1.x, q1.y, q1.z, q1.w};
#pragma unroll
                for (int a = 0; a < 8; a++) {
                    uint64_t m2 = pack2(qa[a]);
#pragma unroll
                    for (int j = 0; j < 4; j++) fma2(s2[a][j], m2, N[j]);
                }
            }

            // Write scores to PsT with rotation swizzle.
            const float scale = 0.125f;
            const int qp0 = (8 * tqg + 4 * tkg) & 127;
            const int qp1 = (qp0 + 4) & 127;
#pragma unroll
            for (int c = 0; c < 8; c++) {
                const int k = 8 * tkg + c;
                const float mv = __ldg(mask + bix * Sn + kt * 128 + k);
                const int cp = c >> 1;
                float va[8];
#pragma unroll
                for (int a = 0; a < 8; a++) {
                    float2 f = unpack2(s2[a][cp]);
                    va[a] = ((c & 1) ? f.y : f.x) * scale + mv;
                }
                *(float4*)&PsT[k * 128 + qp0] =
                    make_float4(va[0], va[1], va[2], va[3]);
                *(float4*)&PsT[k * 128 + qp1] =
                    make_float4(va[4], va[5], va[6], va[7]);
            }
        }
        __syncthreads();

        // ---- softmax: 2 threads per q row (split over k halves) ----
        {
            const int sq = tid & 127;
            const int kh2 = tid >> 7;
            float lm = -1e30f;
#pragma unroll
            for (int kb = 0; kb < 8; kb++) {
                const int kbase = kh2 * 64 + kb * 8;
                const int qpr = (sq + 4 * (kbase >> 3)) & 127;
                const float* p = &PsT[kbase * 128 + qpr];
#pragma unroll
                for (int j = 0; j < 8; j++) lm = fmaxf(lm, p[j * 128]);
            }
            pmax[tid] = lm;
            __syncthreads();

            if (tid < 128) {
                float mt = fmaxf(mrow[tid], fmaxf(pmax[tid], pmax[tid + 128]));
                arow[tid] = __expf(mrow[tid] - mt);
                mrow[tid] = mt;
            }
            __syncthreads();

            const float mt = mrow[sq];
            float ssum = 0.f;
#pragma unroll
            for (int kb = 0; kb < 8; kb++) {
                const int kbase = kh2 * 64 + kb * 8;
                const int qpr = (sq + 4 * (kbase >> 3)) & 127;
                float* p = &PsT[kbase * 128 + qpr];
#pragma unroll
                for (int j = 0; j < 8; j++) {
                    float e = __expf(p[j * 128] - mt);
                    p[j * 128] = e;
                    ssum += e;
                }
            }
            psum[tid] = ssum;
            __syncthreads();

            if (tid < 128)
                lrow[tid] = lrow[tid] * arow[tid] + psum[tid] + psum[tid + 128];
        }
        __syncthreads();

        // ---- PV: 8q x 8d per thread over half the keys ----
        {
#pragma unroll
            for (int a = 0; a < 8; a++) {
                uint64_t a2 = pack2(arow[8 * pqg + a]);
#pragma unroll
                for (int dp = 0; dp < 4; dp++) mul2(ctx2[a][dp], a2);
            }
#pragma unroll 2
            for (int jb = 0; jb < 8; jb++) {
                const int j0 = pkh * 64 + jb * 8;
                const int qp = (8 * pqg + 4 * (j0 >> 3)) & 127;
                const int qpb = (qp + 4) & 127;
#pragma unroll
                for (int ji = 0; ji < 8; ji++) {
                    const int j = j0 + ji;
                    float4 pA = *(const float4*)&PsT[j * 128 + qp];
                    float4 pB = *(const float4*)&PsT[j * 128 + qpb];
                    ulonglong2 vA = *(const ulonglong2*)&Vs[j * 68 + 8 * pdg];
                    ulonglong2 vB = *(const ulonglong2*)&Vs[j * 68 + 8 * pdg + 4];
                    float pa[8] = {pA.x, pA.y, pA.z, pA.w, pB.x, pB.y, pB.z, pB.w};
#pragma unroll
                    for (int a = 0; a < 8; a++) {
                        uint64_t p2 = pack2(pa[a]);
                        fma2(ctx2[a][0], p2, vA.x);
                        fma2(ctx2[a][1], p2, vA.y);
                        fma2(ctx2[a][2], p2, vB.x);
                        fma2(ctx2[a][3], p2, vB.y);
                    }
                }
            }
        }
        __syncthreads();
    }

    // ---- combine split-k halves, normalize, write out ----
    float* scratch = PsT;   // 8192 floats needed, 16384 available
    if (pkh == 1) {
#pragma unroll
        for (int a = 0; a < 8; a++) {
#pragma unroll
            for (int dp = 0; dp < 4; dp++) {
                float2 f = unpack2(ctx2[a][dp]);
                *(float2*)&scratch[(8 * pqg + a) * 64 + 8 * pdg + 2 * dp] = f;
            }
        }
    }
    __syncthreads();
    if (pkh == 0) {
#pragma unroll
        for (int a = 0; a < 8; a++) {
            const int q = 8 * pqg + a;
            const float inv = 1.f / lrow[q];
            const float* sc = &scratch[q * 64 + 8 * pdg];
            float o[8];
#pragma unroll
            for (int dp = 0; dp < 4; dp++) {
                float2 f = unpack2(ctx2[a][dp]);
                o[2 * dp + 0] = (f.x + sc[2 * dp + 0]) * inv;
                o[2 * dp + 1] = (f.y + sc[2 * dp + 1]) * inv;
            }
            float* op = out + ((size_t)bix * Sn + qt * 128 + q) * Dn
                        + h * HDn + 8 * pdg;
            *(float4*)(op) = make_float4(o[0], o[1], o[2], o[3]);
            *(float4*)(op + 4) = make_float4(o[4], o[5], o[6], o[7]);
        }
    }
}

// ---------------------------------------------------------------------------
// Launch
// ---------------------------------------------------------------------------
extern "C" void kernel_launch(void* const* d_in, const int* in_sizes, int n_in,
                              void* d_out, int out_size)
{
    const float* hs   = (const float*)d_in[0];
    const float* mask = (const float*)d_in[1];
    const float* Wq   = (const float*)d_in[2];
    const float* bq   = (const float*)d_in[3];
    const float* Wk   = (const float*)d_in[4];
    const float* bk   = (const float*)d_in[5];
    const float* Wv   = (const float*)d_in[6];
    const float* bv   = (const float*)d_in[7];
    float* out = (float*)d_out;

    cudaFuncSetAttribute(attn_kernel,
                         cudaFuncAttributeMaxDynamicSharedMemorySize, ATTN_SMEM);

    dim3 gemmGrid(Dn / 128, Mtot / 128);   // (8, 64)
    qkv_gemm_kernel<<<gemmGrid, 256>>>(hs, Wq, bq, 0);
    qkv_gemm_kernel<<<gemmGrid, 256>>>(hs, Wk, bk, 1);
    qkv_gemm_kernel<<<gemmGrid, 256>>>(hs, Wv, bv, 2);

    dim3 attnGrid(Sn / 128, Bn * Hn);      // (8, 128)
    attn_kernel<<<attnGrid, 256, ATTN_SMEM>>>(mask, out);
}

// round 8
// speedup vs baseline: 7.5536x; 1.0725x over previous
#include <cuda_runtime.h>
#include <cstdint>

#define Bn 8
#define Sn 1024
#define Dn 1024
#define Hn 16
#define HDn 64
#define Mtot (Bn * Sn)   // 8192

// ---------------------------------------------------------------------------
// Scratch (__device__ globals; allocation-free rule)
// ---------------------------------------------------------------------------
__device__ float g_q[Bn * Hn * Sn * HDn];
__device__ float g_k[Bn * Hn * Sn * HDn];
__device__ float g_v[Bn * Hn * Sn * HDn];

// ---------------------------------------------------------------------------
// Packed f32x2 + cp.async helpers
// ---------------------------------------------------------------------------
__device__ __forceinline__ void fma2(uint64_t& d, uint64_t a, uint64_t b) {
    asm("fma.rn.f32x2 %0, %1, %2, %0;" : "+l"(d) : "l"(a), "l"(b));
}
__device__ __forceinline__ void mul2(uint64_t& d, uint64_t a) {
    asm("mul.rn.f32x2 %0, %0, %1;" : "+l"(d) : "l"(a));
}
__device__ __forceinline__ uint64_t pack2(float x) {
    uint64_t r;
    asm("mov.b64 %0, {%1, %1};" : "=l"(r) : "f"(x));
    return r;
}
__device__ __forceinline__ float2 unpack2(uint64_t v) {
    float lo, hi;
    asm("mov.b64 {%0, %1}, %2;" : "=f"(lo), "=f"(hi) : "l"(v));
    return make_float2(lo, hi);
}
__device__ __forceinline__ uint32_t smem_u32(const void* p) {
    uint32_t a;
    asm("{ .reg .u64 t; cvta.to.shared.u64 t, %1; cvt.u32.u64 %0, t; }"
        : "=r"(a) : "l"(p));
    return a;
}
#define CP_ASYNC16(dst, src) \
    asm volatile("cp.async.cg.shared.global [%0], [%1], 16;" \
                 :: "r"(dst), "l"(src) : "memory")
#define CP_COMMIT() asm volatile("cp.async.commit_group;" ::: "memory")
#define CP_WAIT0()  asm volatile("cp.async.wait_group 0;" ::: "memory")

// ---------------------------------------------------------------------------
// Fused QKV GEMM: one launch, grid (8, 64, 3); z selects {Q,K,V}.
// Hot loop identical to the R5-R7 kernel (measured 97% of fp32 MAC floor).
// ---------------------------------------------------------------------------
__global__ __launch_bounds__(256) void qkv_gemm_fused(
    const float* __restrict__ A,
    const float* __restrict__ Wq, const float* __restrict__ Wk,
    const float* __restrict__ Wv,
    const float* __restrict__ bq, const float* __restrict__ bk,
    const float* __restrict__ bv)
{
    constexpr int K = Dn;
    __shared__ float As[16][128];
    __shared__ float Bs[16][128];

    const int sel = blockIdx.z;
    const float* W    = (sel == 0) ? Wq : (sel == 1) ? Wk : Wv;
    const float* bias = (sel == 0) ? bq : (sel == 1) ? bk : bv;
    float* out        = (sel == 0) ? g_q : (sel == 1) ? g_k : g_v;

    const int tid = threadIdx.x;
    const int blockRow = blockIdx.y * 128;
    const int blockCol = blockIdx.x * 128;

    const int threadRow = (tid / 16) * 8;
    const int threadCol = (tid % 16) * 8;

    uint64_t acc2[8][4];
#pragma unroll
    for (int i = 0; i < 8; i++)
#pragma unroll
        for (int j = 0; j < 4; j++) acc2[i][j] = 0ull;

    for (int k0 = 0; k0 < K; k0 += 16) {
#pragma unroll
        for (int it = 0; it < 2; it++) {
            int lin = tid + it * 256;
            int ra = lin >> 2;
            int ca = (lin & 3) << 2;
            float4 av = *(const float4*)(A + (size_t)(blockRow + ra) * K + k0 + ca);
            As[ca + 0][ra] = av.x;
            As[ca + 1][ra] = av.y;
            As[ca + 2][ra] = av.z;
            As[ca + 3][ra] = av.w;

            int rb = lin >> 5;
            int cb = (lin & 31) << 2;
            *(float4*)&Bs[rb][cb] =
                *(const float4*)(W + (size_t)(k0 + rb) * Dn + blockCol + cb);
        }
        __syncthreads();

#pragma unroll
        for (int kk = 0; kk < 16; kk++) {
            float4 a0 = *(const float4*)&As[kk][threadRow];
            float4 a1 = *(const float4*)&As[kk][threadRow + 4];
            ulonglong2 nA = *(const ulonglong2*)&Bs[kk][threadCol];
            ulonglong2 nB = *(const ulonglong2*)&Bs[kk][threadCol + 4];
            uint64_t N[4] = {nA.x, nA.y, nB.x, nB.y};
            float Ms[8] = {a0.x, a0.y, a0.z, a0.w, a1.x, a1.y, a1.z, a1.w};
#pragma unroll
            for (int i = 0; i < 8; i++) {
                uint64_t m2 = pack2(Ms[i]);
#pragma unroll
                for (int j = 0; j < 4; j++) fma2(acc2[i][j], m2, N[j]);
            }
        }
        __syncthreads();
    }

#pragma unroll
    for (int i = 0; i < 8; i++) {
        int m = blockRow + threadRow + i;
        int b = m >> 10;
        int s = m & 1023;
#pragma unroll
        for (int jp = 0; jp < 2; jp++) {
            int n = blockCol + threadCol + jp * 4;
            int h = n >> 6;
            int hd = n & 63;
            float2 p0 = unpack2(acc2[i][2 * jp]);
            float2 p1 = unpack2(acc2[i][2 * jp + 1]);
            float4 bv4 = *(const float4*)(bias + n);
            float4 v;
            v.x = p0.x + bv4.x;
            v.y = p0.y + bv4.y;
            v.z = p1.x + bv4.z;
            v.w = p1.y + bv4.w;
            *(float4*)(out + (((size_t)(b * Hn + h) * Sn + s) * HDn) + hd) = v;
        }
    }
}

// ---------------------------------------------------------------------------
// Flash attention v5: R7 structure + cp.async V-fill overlapped with QK+softmax.
// grid (Sn/128, B*H) = (8, 128), 256 threads, ~168KB dyn smem.
// ---------------------------------------------------------------------------
#define QST_OFF 0                       // [64][132]
#define KST_OFF 8448                    // [64][132]
#define VS_OFF  16896                   // [128][68]
#define PST_OFF 25600                   // [128][128] rotated
#define MR_OFF  41984
#define LR_OFF  (MR_OFF + 128)
#define AR_OFF  (LR_OFF + 128)
#define PM_OFF  (AR_OFF + 128)          // [256]
#define SU_OFF  (PM_OFF + 256)          // [256]
#define ATTN_SMEM ((SU_OFF + 256) * 4)  // 171520 bytes

__global__ __launch_bounds__(256) void attn_kernel(
    const float* __restrict__ mask, float* __restrict__ out)
{
    extern __shared__ float sm[];
    float* QsT = sm + QST_OFF;
    float* KsT = sm + KST_OFF;
    float* Vs  = sm + VS_OFF;
    float* PsT = sm + PST_OFF;
    float* mrow = sm + MR_OFF;
    float* lrow = sm + LR_OFF;
    float* arow = sm + AR_OFF;
    float* pmax = sm + PM_OFF;
    float* psum = sm + SU_OFF;

    const int tid = threadIdx.x;
    const int qt = blockIdx.x;
    const int bh = blockIdx.y;
    const int bix = bh >> 4;
    const int h = bh & 15;

    const float* Qg = g_q + (size_t)bh * Sn * HDn + (size_t)qt * 128 * HDn;
    const float* Kg = g_k + (size_t)bh * Sn * HDn;
    const float* Vg = g_v + (size_t)bh * Sn * HDn;

    // ---- QsT fill (once): transpose 128q x 64d -> [d][q] ----
#pragma unroll
    for (int i = 0; i < 4; i++) {
        int lin = tid + i * 256;
        int q = lin & 127;
        int db = (lin >> 7) * 8;
        float4 f0 = *(const float4*)(Qg + q * HDn + db);
        float4 f1 = *(const float4*)(Qg + q * HDn + db + 4);
        QsT[(db + 0) * 132 + q] = f0.x;
        QsT[(db + 1) * 132 + q] = f0.y;
        QsT[(db + 2) * 132 + q] = f0.z;
        QsT[(db + 3) * 132 + q] = f0.w;
        QsT[(db + 4) * 132 + q] = f1.x;
        QsT[(db + 5) * 132 + q] = f1.y;
        QsT[(db + 6) * 132 + q] = f1.z;
        QsT[(db + 7) * 132 + q] = f1.w;
    }
    if (tid < 128) { mrow[tid] = -1e30f; lrow[tid] = 0.f; }

    uint64_t ctx2[8][4];
#pragma unroll
    for (int a = 0; a < 8; a++)
#pragma unroll
        for (int dp = 0; dp < 4; dp++) ctx2[a][dp] = 0ull;

    const int tqg = tid >> 4, tkg = tid & 15;
    const int pqg = tid >> 4, pdg = (tid >> 1) & 7, pkh = tid & 1;

    // Per-thread V cp.async mapping (same indices every kt)
    const int vkv = tid >> 1;            // 0..127
    const int vdc = (tid & 1) * 32;      // 0 or 32 (floats)... see below
    __syncthreads();

    for (int kt = 0; kt < Sn / 128; kt++) {
        // ---- KsT fill (LDG+STS transpose) ----
#pragma unroll
        for (int i = 0; i < 4; i++) {
            int lin = tid + i * 256;
            int k = lin & 127;
            int db = (lin >> 7) * 8;
            const float* kr = Kg + (size_t)(kt * 128 + k) * HDn + db;
            float4 f0 = *(const float4*)(kr);
            float4 f1 = *(const float4*)(kr + 4);
            KsT[(db + 0) * 132 + k] = f0.x;
            KsT[(db + 1) * 132 + k] = f0.y;
            KsT[(db + 2) * 132 + k] = f0.z;
            KsT[(db + 3) * 132 + k] = f0.w;
            KsT[(db + 4) * 132 + k] = f1.x;
            KsT[(db + 5) * 132 + k] = f1.y;
            KsT[(db + 6) * 132 + k] = f1.z;
            KsT[(db + 7) * 132 + k] = f1.w;
        }

        // ---- Vs fill via cp.async: overlapped with QK + softmax ----
        // Each thread copies 32 floats = 8 x 16B: half a V row.
        {
            const float* vsrc = Vg + (size_t)(kt * 128 + vkv) * HDn + vdc;
            uint32_t vdst = smem_u32(&Vs[vkv * 68 + vdc]);
#pragma unroll
            for (int c = 0; c < 8; c++)
                CP_ASYNC16(vdst + c * 16, vsrc + c * 4);
            CP_COMMIT();
        }
        __syncthreads();   // KsT ready (V still in flight)

        // ---- QK: 8q x 8k per thread, pair over k ----
        {
            uint64_t s2[8][4];
#pragma unroll
            for (int a = 0; a < 8; a++)
#pragma unroll
                for (int j = 0; j < 4; j++) s2[a][j] = 0ull;

            const float* qbase = QsT + 8 * tqg;
            const float* kbase = KsT + 8 * tkg;
#pragma unroll 4
            for (int d = 0; d < 64; d++) {
                float4 q0 = *(const float4*)(qbase + d * 132);
                float4 q1 = *(const float4*)(qbase + d * 132 + 4);
                ulonglong2 kA = *(const ulonglong2*)(kbase + d * 132);
                ulonglong2 kB = *(const ulonglong2*)(kbase + d * 132 + 4);
                uint64_t N[4] = {kA.x, kA.y, kB.x, kB.y};
                float qa[8] = {q0.x, q0.y, q0.z, q0.w, q1.x, q1.y, q1.z, q1.w};
#pragma unroll
                for (int a = 0; a < 8; a++) {
                    uint64_t m2 = pack2(qa[a]);
#pragma unroll
                    for (int j = 0; j < 4; j++) fma2(s2[a][j], m2, N[j]);
                }
            }

            const float scale = 0.125f;
            const int qp0 = (8 * tqg + 4 * tkg) & 127;
            const int qp1 = (qp0 + 4) & 127;
#pragma unroll
            for (int c = 0; c < 8; c++) {
                const int k = 8 * tkg + c;
                const float mv = __ldg(mask + bix * Sn + kt * 128 + k);
                const int cp = c >> 1;
                float va[8];
#pragma unroll
                for (int a = 0; a < 8; a++) {
                    float2 f = unpack2(s2[a][cp]);
                    va[a] = ((c & 1) ? f.y : f.x) * scale + mv;
                }
                *(float4*)&PsT[k * 128 + qp0] =
                    make_float4(va[0], va[1], va[2], va[3]);
                *(float4*)&PsT[k * 128 + qp1] =
                    make_float4(va[4], va[5], va[6], va[7]);
            }
        }
        __syncthreads();

        // ---- softmax: 2 threads per q row ----
        {
            const int sq = tid & 127;
            const int kh2 = tid >> 7;
            float lm = -1e30f;
#pragma unroll
            for (int kb = 0; kb < 8; kb++) {
                const int kbase = kh2 * 64 + kb * 8;
                const int qpr = (sq + 4 * (kbase >> 3)) & 127;
                const float* p = &PsT[kbase * 128 + qpr];
#pragma unroll
                for (int j = 0; j < 8; j++) lm = fmaxf(lm, p[j * 128]);
            }
            pmax[tid] = lm;
            __syncthreads();

            if (tid < 128) {
                float mt = fmaxf(mrow[tid], fmaxf(pmax[tid], pmax[tid + 128]));
                arow[tid] = __expf(mrow[tid] - mt);
                mrow[tid] = mt;
            }
            __syncthreads();

            const float mt = mrow[sq];
            float ssum = 0.f;
#pragma unroll
            for (int kb = 0; kb < 8; kb++) {
                const int kbase = kh2 * 64 + kb * 8;
                const int qpr = (sq + 4 * (kbase >> 3)) & 127;
                float* p = &PsT[kbase * 128 + qpr];
#pragma unroll
                for (int j = 0; j < 8; j++) {
                    float e = __expf(p[j * 128] - mt);
                    p[j * 128] = e;
                    ssum += e;
                }
            }
            psum[tid] = ssum;
            __syncthreads();

            if (tid < 128)
                lrow[tid] = lrow[tid] * arow[tid] + psum[tid] + psum[tid + 128];
        }
        CP_WAIT0();        // V copies done (per-thread)
        __syncthreads();   // V visible to all

        // ---- PV: 8q x 8d per thread over half the keys ----
        {
#pragma unroll
            for (int a = 0; a < 8; a++) {
                uint64_t a2 = pack2(arow[8 * pqg + a]);
#pragma unroll
                for (int dp = 0; dp < 4; dp++) mul2(ctx2[a][dp], a2);
            }
#pragma unroll 2
            for (int jb = 0; jb < 8; jb++) {
                const int j0 = pkh * 64 + jb * 8;
                const int qp = (8 * pqg + 4 * (j0 >> 3)) & 127;
                const int qpb = (qp + 4) & 127;
#pragma unroll
                for (int ji = 0; ji < 8; ji++) {
                    const int j = j0 + ji;
                    float4 pA = *(const float4*)&PsT[j * 128 + qp];
                    float4 pB = *(const float4*)&PsT[j * 128 + qpb];
                    ulonglong2 vA = *(const ulonglong2*)&Vs[j * 68 + 8 * pdg];
                    ulonglong2 vB = *(const ulonglong2*)&Vs[j * 68 + 8 * pdg + 4];
                    float pa[8] = {pA.x, pA.y, pA.z, pA.w, pB.x, pB.y, pB.z, pB.w};
#pragma unroll
                    for (int a = 0; a < 8; a++) {
                        uint64_t p2 = pack2(pa[a]);
                        fma2(ctx2[a][0], p2, vA.x);
                        fma2(ctx2[a][1], p2, vA.y);
                        fma2(ctx2[a][2], p2, vB.x);
                        fma2(ctx2[a][3], p2, vB.y);
                    }
                }
            }
        }
        __syncthreads();
    }

    // ---- combine split-k halves, normalize, write out ----
    float* scratch = PsT;
    if (pkh == 1) {
#pragma unroll
        for (int a = 0; a < 8; a++) {
#pragma unroll
            for (int dp = 0; dp < 4; dp++) {
                float2 f = unpack2(ctx2[a][dp]);
                *(float2*)&scratch[(8 * pqg + a) * 64 + 8 * pdg + 2 * dp] = f;
            }
        }
    }
    __syncthreads();
    if (pkh == 0) {
#pragma unroll
        for (int a = 0; a < 8; a++) {
            const int q = 8 * pqg + a;
            const float inv = 1.f / lrow[q];
            const float* sc = &scratch[q * 64 + 8 * pdg];
            float o[8];
#pragma unroll
            for (int dp = 0; dp < 4; dp++) {
                float2 f = unpack2(ctx2[a][dp]);
                o[2 * dp + 0] = (f.x + sc[2 * dp + 0]) * inv;
                o[2 * dp + 1] = (f.y + sc[2 * dp + 1]) * inv;
            }
            float* op = out + ((size_t)bix * Sn + qt * 128 + q) * Dn
                        + h * HDn + 8 * pdg;
            *(float4*)(op) = make_float4(o[0], o[1], o[2], o[3]);
            *(float4*)(op + 4) = make_float4(o[4], o[5], o[6], o[7]);
        }
    }
}

// ---------------------------------------------------------------------------
// Launch
// ---------------------------------------------------------------------------
extern "C" void kernel_launch(void* const* d_in, const int* in_sizes, int n_in,
                              void* d_out, int out_size)
{
    const float* hs   = (const float*)d_in[0];
    const float* mask = (const float*)d_in[1];
    const float* Wq   = (const float*)d_in[2];
    const float* bq   = (const float*)d_in[3];
    const float* Wk   = (const float*)d_in[4];
    const float* bk   = (const float*)d_in[5];
    const float* Wv   = (const float*)d_in[6];
    const float* bv   = (const float*)d_in[7];
    float* out = (float*)d_out;

    cudaFuncSetAttribute(attn_kernel,
                         cudaFuncAttributeMaxDynamicSharedMemorySize, ATTN_SMEM);

    dim3 gemmGrid(Dn / 128, Mtot / 128, 3);   // (8, 64, 3) fused
    qkv_gemm_fused<<<gemmGrid, 256>>>(hs, Wq, Wk, Wv, bq, bk, bv);

    dim3 attnGrid(Sn / 128, Bn * Hn);         // (8, 128)
    attn_kernel<<<attnGrid, 256, ATTN_SMEM>>>(mask, out);
}

// round 9
// speedup vs baseline: 7.7054x; 1.0201x over previous
#include <cuda_runtime.h>
#include <cstdint>

#define Bn 8
#define Sn 1024
#define Dn 1024
#define Hn 16
#define HDn 64
#define Mtot (Bn * Sn)   // 8192

// ---------------------------------------------------------------------------
// Scratch (__device__ globals; allocation-free rule)
// ---------------------------------------------------------------------------
__device__ float g_q[Bn * Hn * Sn * HDn];
__device__ float g_k[Bn * Hn * Sn * HDn];
__device__ float g_v[Bn * Hn * Sn * HDn];

// ---------------------------------------------------------------------------
// Packed f32x2 + cp.async helpers
// ---------------------------------------------------------------------------
__device__ __forceinline__ void fma2(uint64_t& d, uint64_t a, uint64_t b) {
    asm("fma.rn.f32x2 %0, %1, %2, %0;" : "+l"(d) : "l"(a), "l"(b));
}
__device__ __forceinline__ void mul2(uint64_t& d, uint64_t a) {
    asm("mul.rn.f32x2 %0, %0, %1;" : "+l"(d) : "l"(a));
}
__device__ __forceinline__ uint64_t pack2(float x) {
    uint64_t r;
    asm("mov.b64 %0, {%1, %1};" : "=l"(r) : "f"(x));
    return r;
}
__device__ __forceinline__ float2 unpack2(uint64_t v) {
    float lo, hi;
    asm("mov.b64 {%0, %1}, %2;" : "=f"(lo), "=f"(hi) : "l"(v));
    return make_float2(lo, hi);
}
__device__ __forceinline__ uint32_t smem_u32(const void* p) {
    uint32_t a;
    asm("{ .reg .u64 t; cvta.to.shared.u64 t, %1; cvt.u32.u64 %0, t; }"
        : "=r"(a) : "l"(p));
    return a;
}
#define CP_ASYNC16(dst, src) \
    asm volatile("cp.async.cg.shared.global [%0], [%1], 16;" \
                 :: "r"(dst), "l"(src) : "memory")
#define CP_COMMIT() asm volatile("cp.async.commit_group;" ::: "memory")
#define CP_WAIT0()  asm volatile("cp.async.wait_group 0;" ::: "memory")

// ---------------------------------------------------------------------------
// Fused QKV GEMM (unchanged from R8 — at the demonstrated MAC-rate ceiling).
// ---------------------------------------------------------------------------
__global__ __launch_bounds__(256) void qkv_gemm_fused(
    const float* __restrict__ A,
    const float* __restrict__ Wq, const float* __restrict__ Wk,
    const float* __restrict__ Wv,
    const float* __restrict__ bq, const float* __restrict__ bk,
    const float* __restrict__ bv)
{
    constexpr int K = Dn;
    __shared__ float As[16][128];
    __shared__ float Bs[16][128];

    const int sel = blockIdx.z;
    const float* W    = (sel == 0) ? Wq : (sel == 1) ? Wk : Wv;
    const float* bias = (sel == 0) ? bq : (sel == 1) ? bk : bv;
    float* out        = (sel == 0) ? g_q : (sel == 1) ? g_k : g_v;

    const int tid = threadIdx.x;
    const int blockRow = blockIdx.y * 128;
    const int blockCol = blockIdx.x * 128;

    const int threadRow = (tid / 16) * 8;
    const int threadCol = (tid % 16) * 8;

    uint64_t acc2[8][4];
#pragma unroll
    for (int i = 0; i < 8; i++)
#pragma unroll
        for (int j = 0; j < 4; j++) acc2[i][j] = 0ull;

    for (int k0 = 0; k0 < K; k0 += 16) {
#pragma unroll
        for (int it = 0; it < 2; it++) {
            int lin = tid + it * 256;
            int ra = lin >> 2;
            int ca = (lin & 3) << 2;
            float4 av = *(const float4*)(A + (size_t)(blockRow + ra) * K + k0 + ca);
            As[ca + 0][ra] = av.x;
            As[ca + 1][ra] = av.y;
            As[ca + 2][ra] = av.z;
            As[ca + 3][ra] = av.w;

            int rb = lin >> 5;
            int cb = (lin & 31) << 2;
            *(float4*)&Bs[rb][cb] =
                *(const float4*)(W + (size_t)(k0 + rb) * Dn + blockCol + cb);
        }
        __syncthreads();

#pragma unroll
        for (int kk = 0; kk < 16; kk++) {
            float4 a0 = *(const float4*)&As[kk][threadRow];
            float4 a1 = *(const float4*)&As[kk][threadRow + 4];
            ulonglong2 nA = *(const ulonglong2*)&Bs[kk][threadCol];
            ulonglong2 nB = *(const ulonglong2*)&Bs[kk][threadCol + 4];
            uint64_t N[4] = {nA.x, nA.y, nB.x, nB.y};
            float Ms[8] = {a0.x, a0.y, a0.z, a0.w, a1.x, a1.y, a1.z, a1.w};
#pragma unroll
            for (int i = 0; i < 8; i++) {
                uint64_t m2 = pack2(Ms[i]);
#pragma unroll
                for (int j = 0; j < 4; j++) fma2(acc2[i][j], m2, N[j]);
            }
        }
        __syncthreads();
    }

#pragma unroll
    for (int i = 0; i < 8; i++) {
        int m = blockRow + threadRow + i;
        int b = m >> 10;
        int s = m & 1023;
#pragma unroll
        for (int jp = 0; jp < 2; jp++) {
            int n = blockCol + threadCol + jp * 4;
            int h = n >> 6;
            int hd = n & 63;
            float2 p0 = unpack2(acc2[i][2 * jp]);
            float2 p1 = unpack2(acc2[i][2 * jp + 1]);
            float4 bv4 = *(const float4*)(bias + n);
            float4 v;
            v.x = p0.x + bv4.x;
            v.y = p0.y + bv4.y;
            v.z = p1.x + bv4.z;
            v.w = p1.y + bv4.w;
            *(float4*)(out + (((size_t)(b * Hn + h) * Sn + s) * HDn) + hd) = v;
        }
    }
}

// ---------------------------------------------------------------------------
// Flash attention v6: register-resident online softmax.
// grid (Sn/128, B*H) = (8, 128), 256 threads, ~167KB dyn smem.
// q-group = 16 threads (tkg 0..15) inside one warp half; they own 8 q rows
// end-to-end: QK scores, softmax state (m/l/alpha in regs, shfl reductions),
// and PV accumulation. PsT written once (exp'd p), read once.
// ---------------------------------------------------------------------------
#define QST_OFF 0                       // [64][132]
#define KST_OFF 8448                    // [64][132]
#define VS_OFF  16896                   // [128][68]
#define PST_OFF 25600                   // [128][128] rotated
#define ATTN_SMEM ((PST_OFF + 128 * 128) * 4)  // 167936 bytes

__global__ __launch_bounds__(256) void attn_kernel(
    const float* __restrict__ mask, float* __restrict__ out)
{
    extern __shared__ float sm[];
    float* QsT = sm + QST_OFF;
    float* KsT = sm + KST_OFF;
    float* Vs  = sm + VS_OFF;
    float* PsT = sm + PST_OFF;

    const int tid = threadIdx.x;
    const int qt = blockIdx.x;
    const int bh = blockIdx.y;
    const int bix = bh >> 4;
    const int h = bh & 15;

    const float* Qg = g_q + (size_t)bh * Sn * HDn + (size_t)qt * 128 * HDn;
    const float* Kg = g_k + (size_t)bh * Sn * HDn;
    const float* Vg = g_v + (size_t)bh * Sn * HDn;

    // ---- QsT fill (once): transpose 128q x 64d -> [d][q] ----
#pragma unroll
    for (int i = 0; i < 4; i++) {
        int lin = tid + i * 256;
        int q = lin & 127;
        int db = (lin >> 7) * 8;
        float4 f0 = *(const float4*)(Qg + q * HDn + db);
        float4 f1 = *(const float4*)(Qg + q * HDn + db + 4);
        QsT[(db + 0) * 132 + q] = f0.x;
        QsT[(db + 1) * 132 + q] = f0.y;
        QsT[(db + 2) * 132 + q] = f0.z;
        QsT[(db + 3) * 132 + q] = f0.w;
        QsT[(db + 4) * 132 + q] = f1.x;
        QsT[(db + 5) * 132 + q] = f1.y;
        QsT[(db + 6) * 132 + q] = f1.z;
        QsT[(db + 7) * 132 + q] = f1.w;
    }

    // Register softmax state (replicated across each 16-lane q-group)
    float mreg[8], lreg[8];
#pragma unroll
    for (int a = 0; a < 8; a++) { mreg[a] = -1e30f; lreg[a] = 0.f; }

    uint64_t ctx2[8][4];
#pragma unroll
    for (int a = 0; a < 8; a++)
#pragma unroll
        for (int dp = 0; dp < 4; dp++) ctx2[a][dp] = 0ull;

    const int tqg = tid >> 4, tkg = tid & 15;
    const int pqg = tid >> 4, pdg = (tid >> 1) & 7, pkh = tid & 1;

    const int vkv = tid >> 1;
    const int vdc = (tid & 1) * 32;
    __syncthreads();

    for (int kt = 0; kt < Sn / 128; kt++) {
        // ---- KsT fill (LDG+STS transpose) ----
#pragma unroll
        for (int i = 0; i < 4; i++) {
            int lin = tid + i * 256;
            int k = lin & 127;
            int db = (lin >> 7) * 8;
            const float* kr = Kg + (size_t)(kt * 128 + k) * HDn + db;
            float4 f0 = *(const float4*)(kr);
            float4 f1 = *(const float4*)(kr + 4);
            KsT[(db + 0) * 132 + k] = f0.x;
            KsT[(db + 1) * 132 + k] = f0.y;
            KsT[(db + 2) * 132 + k] = f0.z;
            KsT[(db + 3) * 132 + k] = f0.w;
            KsT[(db + 4) * 132 + k] = f1.x;
            KsT[(db + 5) * 132 + k] = f1.y;
            KsT[(db + 6) * 132 + k] = f1.z;
            KsT[(db + 7) * 132 + k] = f1.w;
        }

        // ---- Vs fill via cp.async (overlapped with QK) ----
        {
            const float* vsrc = Vg + (size_t)(kt * 128 + vkv) * HDn + vdc;
            uint32_t vdst = smem_u32(&Vs[vkv * 68 + vdc]);
#pragma unroll
            for (int c = 0; c < 8; c++)
                CP_ASYNC16(vdst + c * 16, vsrc + c * 4);
            CP_COMMIT();
        }
        __syncthreads();   // KsT ready; PsT free (prev PV done)

        // ---- QK: 8q x 8k per thread ----
        uint64_t s2[8][4];
#pragma unroll
        for (int a = 0; a < 8; a++)
#pragma unroll
            for (int j = 0; j < 4; j++) s2[a][j] = 0ull;
        {
            const float* qbase = QsT + 8 * tqg;
            const float* kbase = KsT + 8 * tkg;
#pragma unroll 4
            for (int d = 0; d < 64; d++) {
                float4 q0 = *(const float4*)(qbase + d * 132);
                float4 q1 = *(const float4*)(qbase + d * 132 + 4);
                ulonglong2 kA = *(const ulonglong2*)(kbase + d * 132);
                ulonglong2 kB = *(const ulonglong2*)(kbase + d * 132 + 4);
                uint64_t N[4] = {kA.x, kA.y, kB.x, kB.y};
                float qa[8] = {q0.x, q0.y, q0.z, q0.w, q1.x, q1.y, q1.z, q1.w};
#pragma unroll
                for (int a = 0; a < 8; a++) {
                    uint64_t m2 = pack2(qa[a]);
#pragma unroll
                    for (int j = 0; j < 4; j++) fma2(s2[a][j], m2, N[j]);
                }
            }
        }

        // ---- register softmax epilogue ----
        {
            const float scale = 0.125f;
            // masked+scaled scores: sv[a][c], k = 8*tkg + c
            float sv[8][8];
            float mk[8];
#pragma unroll
            for (int c = 0; c < 8; c++)
                mk[c] = __ldg(mask + bix * Sn + kt * 128 + 8 * tkg + c);
#pragma unroll
            for (int a = 0; a < 8; a++) {
#pragma unroll
                for (int cp = 0; cp < 4; cp++) {
                    float2 f = unpack2(s2[a][cp]);
                    sv[a][2 * cp + 0] = f.x * scale + mk[2 * cp + 0];
                    sv[a][2 * cp + 1] = f.y * scale + mk[2 * cp + 1];
                }
            }
            // row max over this kt: local 8, then shfl over 16 lanes
#pragma unroll
            for (int a = 0; a < 8; a++) {
                float lm = sv[a][0];
#pragma unroll
                for (int c = 1; c < 8; c++) lm = fmaxf(lm, sv[a][c]);
#pragma unroll
                for (int m = 1; m < 16; m <<= 1)
                    lm = fmaxf(lm, __shfl_xor_sync(0xffffffffu, lm, m));
                const float mt = fmaxf(mreg[a], lm);
                const float alpha = __expf(mreg[a] - mt);
                mreg[a] = mt;
                // exp in registers + local sum
                float ls = 0.f;
#pragma unroll
                for (int c = 0; c < 8; c++) {
                    float e = __expf(sv[a][c] - mt);
                    sv[a][c] = e;
                    ls += e;
                }
#pragma unroll
                for (int m = 1; m < 16; m <<= 1)
                    ls += __shfl_xor_sync(0xffffffffu, ls, m);
                lreg[a] = lreg[a] * alpha + ls;
                // rescale ctx by alpha (same thread owns same q rows in PV)
                uint64_t a2 = pack2(alpha);
#pragma unroll
                for (int dp = 0; dp < 4; dp++) mul2(ctx2[a][dp], a2);
            }
            // store exp'd p to PsT (rotated)
            const int qp0 = (8 * tqg + 4 * tkg) & 127;
            const int qp1 = (qp0 + 4) & 127;
#pragma unroll
            for (int c = 0; c < 8; c++) {
                const int k = 8 * tkg + c;
                *(float4*)&PsT[k * 128 + qp0] =
                    make_float4(sv[0][c], sv[1][c], sv[2][c], sv[3][c]);
                *(float4*)&PsT[k * 128 + qp1] =
                    make_float4(sv[4][c], sv[5][c], sv[6][c], sv[7][c]);
            }
        }
        CP_WAIT0();        // V landed
        __syncthreads();   // PsT + Vs visible

        // ---- PV: 8q x 8d per thread over half the keys ----
        {
#pragma unroll 2
            for (int jb = 0; jb < 8; jb++) {
                const int j0 = pkh * 64 + jb * 8;
                const int qp = (8 * pqg + 4 * (j0 >> 3)) & 127;
                const int qpb = (qp + 4) & 127;
#pragma unroll
                for (int ji = 0; ji < 8; ji++) {
                    const int j = j0 + ji;
                    float4 pA = *(const float4*)&PsT[j * 128 + qp];
                    float4 pB = *(const float4*)&PsT[j * 128 + qpb];
                    ulonglong2 vA = *(const ulonglong2*)&Vs[j * 68 + 8 * pdg];
                    ulonglong2 vB = *(const ulonglong2*)&Vs[j * 68 + 8 * pdg + 4];
                    float pa[8] = {pA.x, pA.y, pA.z, pA.w, pB.x, pB.y, pB.z, pB.w};
#pragma unroll
                    for (int a = 0; a < 8; a++) {
                        uint64_t p2 = pack2(pa[a]);
                        fma2(ctx2[a][0], p2, vA.x);
                        fma2(ctx2[a][1], p2, vA.y);
                        fma2(ctx2[a][2], p2, vB.x);
                        fma2(ctx2[a][3], p2, vB.y);
                    }
                }
            }
        }
        __syncthreads();   // PV done; next kt may overwrite KsT/Vs/PsT
    }

    // ---- combine split-k halves, normalize, write out ----
    float* scratch = PsT;
    if (pkh == 1) {
#pragma unroll
        for (int a = 0; a < 8; a++) {
#pragma unroll
            for (int dp = 0; dp < 4; dp++) {
                float2 f = unpack2(ctx2[a][dp]);
                *(float2*)&scratch[(8 * pqg + a) * 64 + 8 * pdg + 2 * dp] = f;
            }
        }
    }
    __syncthreads();
    if (pkh == 0) {
#pragma unroll
        for (int a = 0; a < 8; a++) {
            const int q = 8 * pqg + a;
            const float inv = 1.f / lreg[a];
            const float* sc = &scratch[q * 64 + 8 * pdg];
            float o[8];
#pragma unroll
            for (int dp = 0; dp < 4; dp++) {
                float2 f = unpack2(ctx2[a][dp]);
                o[2 * dp + 0] = (f.x + sc[2 * dp + 0]) * inv;
                o[2 * dp + 1] = (f.y + sc[2 * dp + 1]) * inv;
            }
            float* op = out + ((size_t)bix * Sn + qt * 128 + q) * Dn
                        + h * HDn + 8 * pdg;
            *(float4*)(op) = make_float4(o[0], o[1], o[2], o[3]);
            *(float4*)(op + 4) = make_float4(o[4], o[5], o[6], o[7]);
        }
    }
}

// ---------------------------------------------------------------------------
// Launch
// ---------------------------------------------------------------------------
extern "C" void kernel_launch(void* const* d_in, const int* in_sizes, int n_in,
                              void* d_out, int out_size)
{
    const float* hs   = (const float*)d_in[0];
    const float* mask = (const float*)d_in[1];
    const float* Wq   = (const float*)d_in[2];
    const float* bq   = (const float*)d_in[3];
    const float* Wk   = (const float*)d_in[4];
    const float* bk   = (const float*)d_in[5];
    const float* Wv   = (const float*)d_in[6];
    const float* bv   = (const float*)d_in[7];
    float* out = (float*)d_out;

    cudaFuncSetAttribute(attn_kernel,
                         cudaFuncAttributeMaxDynamicSharedMemorySize, ATTN_SMEM);

    dim3 gemmGrid(Dn / 128, Mtot / 128, 3);   // fused QKV
    qkv_gemm_fused<<<gemmGrid, 256>>>(hs, Wq, Wk, Wv, bq, bk, bv);

    dim3 attnGrid(Sn / 128, Bn * Hn);
    attn_kernel<<<attnGrid, 256, ATTN_SMEM>>>(mask, out);
}

// round 10
// speedup vs baseline: 7.7880x; 1.0107x over previous
#include <cuda_runtime.h>
#include <cstdint>

#define Bn 8
#define Sn 1024
#define Dn 1024
#define Hn 16
#define HDn 64
#define Mtot (Bn * Sn)   // 8192

// ---------------------------------------------------------------------------
// Scratch (__device__ globals; allocation-free rule)
// ---------------------------------------------------------------------------
__device__ float g_q[Bn * Hn * Sn * HDn];
__device__ float g_k[Bn * Hn * Sn * HDn];
__device__ float g_v[Bn * Hn * Sn * HDn];

// ---------------------------------------------------------------------------
// Packed f32x2 + cp.async helpers
// ---------------------------------------------------------------------------
__device__ __forceinline__ void fma2(uint64_t& d, uint64_t a, uint64_t b) {
    asm("fma.rn.f32x2 %0, %1, %2, %0;" : "+l"(d) : "l"(a), "l"(b));
}
__device__ __forceinline__ void mul2(uint64_t& d, uint64_t a) {
    asm("mul.rn.f32x2 %0, %0, %1;" : "+l"(d) : "l"(a));
}
__device__ __forceinline__ uint64_t pack2(float x) {
    uint64_t r;
    asm("mov.b64 %0, {%1, %1};" : "=l"(r) : "f"(x));
    return r;
}
__device__ __forceinline__ float2 unpack2(uint64_t v) {
    float lo, hi;
    asm("mov.b64 {%0, %1}, %2;" : "=f"(lo), "=f"(hi) : "l"(v));
    return make_float2(lo, hi);
}
__device__ __forceinline__ uint32_t smem_u32(const void* p) {
    uint32_t a;
    asm("{ .reg .u64 t; cvta.to.shared.u64 t, %1; cvt.u32.u64 %0, t; }"
        : "=r"(a) : "l"(p));
    return a;
}
#define CP_ASYNC16(dst, src) \
    asm volatile("cp.async.cg.shared.global [%0], [%1], 16;" \
                 :: "r"(dst), "l"(src) : "memory")
#define CP_COMMIT() asm volatile("cp.async.commit_group;" ::: "memory")
#define CP_WAIT0()  asm volatile("cp.async.wait_group 0;" ::: "memory")

// ---------------------------------------------------------------------------
// Fused QKV GEMM (unchanged — at the fp32 MAC-rate ceiling).
// ---------------------------------------------------------------------------
__global__ __launch_bounds__(256) void qkv_gemm_fused(
    const float* __restrict__ A,
    const float* __restrict__ Wq, const float* __restrict__ Wk,
    const float* __restrict__ Wv,
    const float* __restrict__ bq, const float* __restrict__ bk,
    const float* __restrict__ bv)
{
    constexpr int K = Dn;
    __shared__ float As[16][128];
    __shared__ float Bs[16][128];

    const int sel = blockIdx.z;
    const float* W    = (sel == 0) ? Wq : (sel == 1) ? Wk : Wv;
    const float* bias = (sel == 0) ? bq : (sel == 1) ? bk : bv;
    float* out        = (sel == 0) ? g_q : (sel == 1) ? g_k : g_v;

    const int tid = threadIdx.x;
    const int blockRow = blockIdx.y * 128;
    const int blockCol = blockIdx.x * 128;

    const int threadRow = (tid / 16) * 8;
    const int threadCol = (tid % 16) * 8;

    uint64_t acc2[8][4];
#pragma unroll
    for (int i = 0; i < 8; i++)
#pragma unroll
        for (int j = 0; j < 4; j++) acc2[i][j] = 0ull;

    for (int k0 = 0; k0 < K; k0 += 16) {
#pragma unroll
        for (int it = 0; it < 2; it++) {
            int lin = tid + it * 256;
            int ra = lin >> 2;
            int ca = (lin & 3) << 2;
            float4 av = *(const float4*)(A + (size_t)(blockRow + ra) * K + k0 + ca);
            As[ca + 0][ra] = av.x;
            As[ca + 1][ra] = av.y;
            As[ca + 2][ra] = av.z;
            As[ca + 3][ra] = av.w;

            int rb = lin >> 5;
            int cb = (lin & 31) << 2;
            *(float4*)&Bs[rb][cb] =
                *(const float4*)(W + (size_t)(k0 + rb) * Dn + blockCol + cb);
        }
        __syncthreads();

#pragma unroll
        for (int kk = 0; kk < 16; kk++) {
            float4 a0 = *(const float4*)&As[kk][threadRow];
            float4 a1 = *(const float4*)&As[kk][threadRow + 4];
            ulonglong2 nA = *(const ulonglong2*)&Bs[kk][threadCol];
            ulonglong2 nB = *(const ulonglong2*)&Bs[kk][threadCol + 4];
            uint64_t N[4] = {nA.x, nA.y, nB.x, nB.y};
            float Ms[8] = {a0.x, a0.y, a0.z, a0.w, a1.x, a1.y, a1.z, a1.w};
#pragma unroll
            for (int i = 0; i < 8; i++) {
                uint64_t m2 = pack2(Ms[i]);
#pragma unroll
                for (int j = 0; j < 4; j++) fma2(acc2[i][j], m2, N[j]);
            }
        }
        __syncthreads();
    }

#pragma unroll
    for (int i = 0; i < 8; i++) {
        int m = blockRow + threadRow + i;
        int b = m >> 10;
        int s = m & 1023;
#pragma unroll
        for (int jp = 0; jp < 2; jp++) {
            int n = blockCol + threadCol + jp * 4;
            int h = n >> 6;
            int hd = n & 63;
            float2 p0 = unpack2(acc2[i][2 * jp]);
            float2 p1 = unpack2(acc2[i][2 * jp + 1]);
            float4 bv4 = *(const float4*)(bias + n);
            float4 v;
            v.x = p0.x + bv4.x;
            v.y = p0.y + bv4.y;
            v.z = p1.x + bv4.z;
            v.w = p1.y + bv4.w;
            *(float4*)(out + (((size_t)(b * Hn + h) * Sn + s) * HDn) + hd) = v;
        }
    }
}

// ---------------------------------------------------------------------------
// Flash attention v7: k-tile 64, 128 threads, ~101KB smem -> 2 blocks/SM.
// Thread (tqg=tid>>3, tkg=tid&7): owns q rows 8tqg..+7 end-to-end.
// QK: 8q x 8k x 64d; softmax in regs (shfl over 8 lanes); PsT write-once;
// PV: 8q x 8d over all 64 keys (no split-k, no final combine).
// ---------------------------------------------------------------------------
#define QST_OFF 0                        // [64][132]
#define KST_OFF 8448                     // [64][68]
#define VS_OFF  (8448 + 4352)            // [64][68]
#define PST_OFF (8448 + 2 * 4352)        // [64 k][128 q] rotated
#define ATTN_SMEM ((PST_OFF + 64 * 128) * 4)   // 101376 bytes

__global__ __launch_bounds__(128) void attn_kernel(
    const float* __restrict__ mask, float* __restrict__ out)
{
    extern __shared__ float sm[];
    float* QsT = sm + QST_OFF;
    float* KsT = sm + KST_OFF;
    float* Vs  = sm + VS_OFF;
    float* PsT = sm + PST_OFF;

    const int tid = threadIdx.x;
    const int qt = blockIdx.x;
    const int bh = blockIdx.y;
    const int bix = bh >> 4;
    const int h = bh & 15;

    const float* Qg = g_q + (size_t)bh * Sn * HDn + (size_t)qt * 128 * HDn;
    const float* Kg = g_k + (size_t)bh * Sn * HDn;
    const float* Vg = g_v + (size_t)bh * Sn * HDn;

    // ---- QsT fill (once): transpose 128q x 64d -> [d][q] ----
#pragma unroll
    for (int i = 0; i < 8; i++) {
        int lin = tid + i * 128;
        int q = lin & 127;
        int db = (lin >> 7) * 8;
        float4 f0 = *(const float4*)(Qg + q * HDn + db);
        float4 f1 = *(const float4*)(Qg + q * HDn + db + 4);
        QsT[(db + 0) * 132 + q] = f0.x;
        QsT[(db + 1) * 132 + q] = f0.y;
        QsT[(db + 2) * 132 + q] = f0.z;
        QsT[(db + 3) * 132 + q] = f0.w;
        QsT[(db + 4) * 132 + q] = f1.x;
        QsT[(db + 5) * 132 + q] = f1.y;
        QsT[(db + 6) * 132 + q] = f1.z;
        QsT[(db + 7) * 132 + q] = f1.w;
    }

    float mreg[8], lreg[8];
#pragma unroll
    for (int a = 0; a < 8; a++) { mreg[a] = -1e30f; lreg[a] = 0.f; }

    uint64_t ctx2[8][4];
#pragma unroll
    for (int a = 0; a < 8; a++)
#pragma unroll
        for (int dp = 0; dp < 4; dp++) ctx2[a][dp] = 0ull;

    const int tqg = tid >> 3, tkg = tid & 7;
    const int vkv = tid >> 1;
    const int vdc = (tid & 1) * 32;
    __syncthreads();

    for (int kt = 0; kt < Sn / 64; kt++) {
        // ---- KsT fill (LDG+STS transpose): 64k x 64d ----
#pragma unroll
        for (int i = 0; i < 4; i++) {
            int lin = tid + i * 128;          // 0..511
            int k = lin & 63;
            int db = (lin >> 6) * 8;          // 0..56
            const float* kr = Kg + (size_t)(kt * 64 + k) * HDn + db;
            float4 f0 = *(const float4*)(kr);
            float4 f1 = *(const float4*)(kr + 4);
            KsT[(db + 0) * 68 + k] = f0.x;
            KsT[(db + 1) * 68 + k] = f0.y;
            KsT[(db + 2) * 68 + k] = f0.z;
            KsT[(db + 3) * 68 + k] = f0.w;
            KsT[(db + 4) * 68 + k] = f1.x;
            KsT[(db + 5) * 68 + k] = f1.y;
            KsT[(db + 6) * 68 + k] = f1.z;
            KsT[(db + 7) * 68 + k] = f1.w;
        }

        // ---- Vs fill via cp.async (overlapped with QK) ----
        {
            const float* vsrc = Vg + (size_t)(kt * 64 + vkv) * HDn + vdc;
            uint32_t vdst = smem_u32(&Vs[vkv * 68 + vdc]);
#pragma unroll
            for (int c = 0; c < 8; c++)
                CP_ASYNC16(vdst + c * 16, vsrc + c * 4);
            CP_COMMIT();
        }
        __syncthreads();   // KsT ready; PsT free (prev PV done)

        // ---- QK: 8q x 8k per thread over 64 d ----
        uint64_t s2[8][4];
#pragma unroll
        for (int a = 0; a < 8; a++)
#pragma unroll
            for (int j = 0; j < 4; j++) s2[a][j] = 0ull;
        {
            const float* qbase = QsT + 8 * tqg;
            const float* kbase = KsT + 8 * tkg;
#pragma unroll 4
            for (int d = 0; d < 64; d++) {
                float4 q0 = *(const float4*)(qbase + d * 132);
                float4 q1 = *(const float4*)(qbase + d * 132 + 4);
                ulonglong2 kA = *(const ulonglong2*)(kbase + d * 68);
                ulonglong2 kB = *(const ulonglong2*)(kbase + d * 68 + 4);
                uint64_t N[4] = {kA.x, kA.y, kB.x, kB.y};
                float qa[8] = {q0.x, q0.y, q0.z, q0.w, q1.x, q1.y, q1.z, q1.w};
#pragma unroll
                for (int a = 0; a < 8; a++) {
                    uint64_t m2 = pack2(qa[a]);
#pragma unroll
                    for (int j = 0; j < 4; j++) fma2(s2[a][j], m2, N[j]);
                }
            }
        }

        // ---- register softmax (shfl over the 8 lanes of the q-group) ----
        {
            const float scale = 0.125f;
            float sv[8][8];
            float mk[8];
#pragma unroll
            for (int c = 0; c < 8; c++)
                mk[c] = __ldg(mask + bix * Sn + kt * 64 + 8 * tkg + c);
#pragma unroll
            for (int a = 0; a < 8; a++) {
#pragma unroll
                for (int cp = 0; cp < 4; cp++) {
                    float2 f = unpack2(s2[a][cp]);
                    sv[a][2 * cp + 0] = f.x * scale + mk[2 * cp + 0];
                    sv[a][2 * cp + 1] = f.y * scale + mk[2 * cp + 1];
                }
            }
#pragma unroll
            for (int a = 0; a < 8; a++) {
                float lm = sv[a][0];
#pragma unroll
                for (int c = 1; c < 8; c++) lm = fmaxf(lm, sv[a][c]);
#pragma unroll
                for (int m = 1; m < 8; m <<= 1)
                    lm = fmaxf(lm, __shfl_xor_sync(0xffffffffu, lm, m));
                const float mt = fmaxf(mreg[a], lm);
                const float alpha = __expf(mreg[a] - mt);
                mreg[a] = mt;
                float ls = 0.f;
#pragma unroll
                for (int c = 0; c < 8; c++) {
                    float e = __expf(sv[a][c] - mt);
                    sv[a][c] = e;
                    ls += e;
                }
#pragma unroll
                for (int m = 1; m < 8; m <<= 1)
                    ls += __shfl_xor_sync(0xffffffffu, ls, m);
                lreg[a] = lreg[a] * alpha + ls;
                uint64_t a2 = pack2(alpha);
#pragma unroll
                for (int dp = 0; dp < 4; dp++) mul2(ctx2[a][dp], a2);
            }
            // store exp'd p to PsT (rotated)
            const int qp0 = (8 * tqg + 4 * tkg) & 127;
            const int qp1 = (qp0 + 4) & 127;
#pragma unroll
            for (int c = 0; c < 8; c++) {
                const int k = 8 * tkg + c;
                *(float4*)&PsT[k * 128 + qp0] =
                    make_float4(sv[0][c], sv[1][c], sv[2][c], sv[3][c]);
                *(float4*)&PsT[k * 128 + qp1] =
                    make_float4(sv[4][c], sv[5][c], sv[6][c], sv[7][c]);
            }
        }
        CP_WAIT0();
        __syncthreads();   // PsT + Vs visible

        // ---- PV: 8q x 8d per thread over all 64 keys ----
        {
#pragma unroll 2
            for (int jb = 0; jb < 8; jb++) {
                const int j0 = jb * 8;
                const int qp = (8 * tqg + 4 * jb) & 127;
                const int qpb = (qp + 4) & 127;
#pragma unroll
                for (int ji = 0; ji < 8; ji++) {
                    const int j = j0 + ji;
                    float4 pA = *(const float4*)&PsT[j * 128 + qp];
                    float4 pB = *(const float4*)&PsT[j * 128 + qpb];
                    ulonglong2 vA = *(const ulonglong2*)&Vs[j * 68 + 8 * tkg];
                    ulonglong2 vB = *(const ulonglong2*)&Vs[j * 68 + 8 * tkg + 4];
                    float pa[8] = {pA.x, pA.y, pA.z, pA.w, pB.x, pB.y, pB.z, pB.w};
#pragma unroll
                    for (int a = 0; a < 8; a++) {
                        uint64_t p2 = pack2(pa[a]);
                        fma2(ctx2[a][0], p2, vA.x);
                        fma2(ctx2[a][1], p2, vA.y);
                        fma2(ctx2[a][2], p2, vB.x);
                        fma2(ctx2[a][3], p2, vB.y);
                    }
                }
            }
        }
        __syncthreads();   // PV done; next kt overwrites KsT/Vs/PsT
    }

    // ---- normalize + write out (no split-k combine) ----
#pragma unroll
    for (int a = 0; a < 8; a++) {
        const int q = 8 * tqg + a;
        const float inv = 1.f / lreg[a];
        float o[8];
#pragma unroll
        for (int dp = 0; dp < 4; dp++) {
            float2 f = unpack2(ctx2[a][dp]);
            o[2 * dp + 0] = f.x * inv;
            o[2 * dp + 1] = f.y * inv;
        }
        float* op = out + ((size_t)bix * Sn + qt * 128 + q) * Dn
                    + h * HDn + 8 * tkg;
        *(float4*)(op) = make_float4(o[0], o[1], o[2], o[3]);
        *(float4*)(op + 4) = make_float4(o[4], o[5], o[6], o[7]);
    }
}

// ---------------------------------------------------------------------------
// Launch
// ---------------------------------------------------------------------------
extern "C" void kernel_launch(void* const* d_in, const int* in_sizes, int n_in,
                              void* d_out, int out_size)
{
    const float* hs   = (const float*)d_in[0];
    const float* mask = (const float*)d_in[1];
    const float* Wq   = (const float*)d_in[2];
    const float* bq   = (const float*)d_in[3];
    const float* Wk   = (const float*)d_in[4];
    const float* bk   = (const float*)d_in[5];
    const float* Wv   = (const float*)d_in[6];
    const float* bv   = (const float*)d_in[7];
    float* out = (float*)d_out;

    cudaFuncSetAttribute(attn_kernel,
                         cudaFuncAttributeMaxDynamicSharedMemorySize, ATTN_SMEM);

    dim3 gemmGrid(Dn / 128, Mtot / 128, 3);   // fused QKV
    qkv_gemm_fused<<<gemmGrid, 256>>>(hs, Wq, Wk, Wv, bq, bk, bv);

    dim3 attnGrid(Sn / 128, Bn * Hn);         // (8, 128), 128-thread blocks
    attn_kernel<<<attnGrid, 128, ATTN_SMEM>>>(mask, out);
}